// round 10
// baseline (speedup 1.0000x reference)
#include <cuda_runtime.h>
#include <cuda_bf16.h>
#include <math.h>
#include <stdint.h>

// Problem constants
#define B_   2
#define T_   2048
#define C_   2048
#define H_   32
#define HK_  4
#define D_   64
#define MROWS (B_ * T_)          // 4096

// ---------------- scratch (static device globals; no allocation) ----------
__device__ float g_qraw[(long long)MROWS * (H_ * D_)];
__device__ float g_kraw[(long long)MROWS * (HK_ * D_)];
__device__ float g_vraw[(long long)MROWS * (HK_ * D_)];

__device__ __nv_bfloat16 g_xh[(long long)MROWS * C_],  g_xl[(long long)MROWS * C_];
__device__ __nv_bfloat16 g_oh[(long long)MROWS * C_],  g_ol[(long long)MROWS * C_];
__device__ __nv_bfloat16 g_wqh[(long long)(H_*D_) * C_],  g_wql[(long long)(H_*D_) * C_];
__device__ __nv_bfloat16 g_wkh[(long long)(HK_*D_) * C_], g_wkl[(long long)(HK_*D_) * C_];
__device__ __nv_bfloat16 g_wvh[(long long)(HK_*D_) * C_], g_wvl[(long long)(HK_*D_) * C_];
__device__ __nv_bfloat16 g_woh[(long long)C_ * (H_*D_)],  g_wol[(long long)C_ * (H_*D_)];
__device__ __nv_bfloat16 g_qh[(long long)B_*H_*T_*D_],  g_ql[(long long)B_*H_*T_*D_];
__device__ __nv_bfloat16 g_kh[(long long)B_*HK_*T_*D_], g_kl[(long long)B_*HK_*T_*D_];
__device__ __nv_bfloat16 g_vh[(long long)B_*HK_*T_*D_], g_vl[(long long)B_*HK_*T_*D_];

// ===========================================================================
// helpers
// ===========================================================================
__device__ __forceinline__ uint32_t smem_u32(const void* p) {
    uint32_t a;
    asm("{ .reg .u64 t; cvta.to.shared.u64 t, %1; cvt.u32.u64 %0, t; }"
        : "=r"(a) : "l"(p));
    return a;
}
__device__ __forceinline__ void ldsm_x4(uint32_t* r, uint32_t addr) {
    asm volatile("ldmatrix.sync.aligned.m8n8.x4.shared.b16 {%0,%1,%2,%3}, [%4];"
        : "=r"(r[0]), "=r"(r[1]), "=r"(r[2]), "=r"(r[3]) : "r"(addr));
}
__device__ __forceinline__ void mma16816(float* c, const uint32_t* a, const uint32_t* b) {
    asm volatile(
        "mma.sync.aligned.m16n8k16.row.col.f32.bf16.bf16.f32 "
        "{%0,%1,%2,%3}, {%4,%5,%6,%7}, {%8,%9}, {%0,%1,%2,%3};"
        : "+f"(c[0]), "+f"(c[1]), "+f"(c[2]), "+f"(c[3])
        : "r"(a[0]), "r"(a[1]), "r"(a[2]), "r"(a[3]), "r"(b[0]), "r"(b[1]));
}
__device__ __forceinline__ void split_pair(float a, float b, uint32_t& hi, uint32_t& lo) {
    __nv_bfloat162 h = __floats2bfloat162_rn(a, b);
    float ra = a - __bfloat162float(h.x);
    float rb = b - __bfloat162float(h.y);
    __nv_bfloat162 l = __floats2bfloat162_rn(ra, rb);
    hi = *(uint32_t*)&h;
    lo = *(uint32_t*)&l;
}
__device__ __forceinline__ void cp_async16(uint32_t dst, const void* src) {
    asm volatile("cp.async.cg.shared.global [%0], [%1], 16;" :: "r"(dst), "l"(src));
}
#define CP_COMMIT() asm volatile("cp.async.commit_group;" ::: "memory")
#define CP_WAIT1()  asm volatile("cp.async.wait_group 1;" ::: "memory")
#define CP_WAIT0()  asm volatile("cp.async.wait_group 0;" ::: "memory")

// ===========================================================================
// fp32 -> bf16 hi/lo global split
// ===========================================================================
__global__ void split_f32(const float* __restrict__ src,
                          __nv_bfloat16* __restrict__ hi,
                          __nv_bfloat16* __restrict__ lo, int n8)
{
    int i = blockIdx.x * blockDim.x + threadIdx.x;
    if (i >= n8) return;
    const float4* p = (const float4*)src + 2 * (size_t)i;
    float4 f0 = p[0], f1 = p[1];
    uint4 h, l;
    split_pair(f0.x, f0.y, h.x, l.x);
    split_pair(f0.z, f0.w, h.y, l.y);
    split_pair(f1.x, f1.y, h.z, l.z);
    split_pair(f1.z, f1.w, h.w, l.w);
    ((uint4*)hi)[i] = h;
    ((uint4*)lo)[i] = l;
}

// ===========================================================================
// GEMM core: 128x128 block, bf16x3, K=2048, 3-stage cp.async, 1 sync/chunk.
// 256 threads = 8 warps (4m x 2n), warp tile 32x64.
// ===========================================================================
#define GP 40
#define ST_AHI 0
#define ST_ALO (128 * GP)
#define ST_WHI (2 * 128 * GP)
#define ST_WLO (3 * 128 * GP)
#define STAGE_HW (4 * 128 * GP)          // 20480 hw = 40960 B
#define GEMM_SMEM (3 * STAGE_HW * 2)     // 122880 B

__device__ __forceinline__ void gemm_core(
    const uint16_t* __restrict__ Ahi, const uint16_t* __restrict__ Alo,
    const uint16_t* __restrict__ Whi, const uint16_t* __restrict__ Wlo,
    float* __restrict__ Cout, int N, int bm, int bn, uint16_t* smem)
{
    const int K = C_;
    const uint32_t sbase = smem_u32(smem);
    const int tid  = threadIdx.x;
    const int wid  = tid >> 5;
    const int lane = tid & 31;
    const int wm   = wid & 3;
    const int wn   = wid >> 2;

    float acc[2][8][4];
#pragma unroll
    for (int i = 0; i < 2; i++)
#pragma unroll
        for (int j = 0; j < 8; j++)
#pragma unroll
            for (int q = 0; q < 4; q++) acc[i][j][q] = 0.f;

    const int a_row_in = ((lane >> 3) & 1) * 8 + (lane & 7);
    const int a_koff   = (lane >> 4) * 8;
    const int b_row_in = ((lane >> 4) & 1) * 8 + (lane & 7);
    const int b_koff   = ((lane >> 3) & 1) * 8;

#define GEMM_ISSUE(c) do {                                                    \
        int k0_ = (c) * 32;                                                   \
        uint32_t sb_ = sbase + (((c) % 3) * STAGE_HW) * 2;                     \
        _Pragma("unroll")                                                      \
        for (int r_ = 0; r_ < 2; r_++) {                                      \
            int e_  = tid + r_ * 256;                                          \
            int row = e_ >> 2;                                                 \
            int ch  = e_ & 3;                                                  \
            size_t gA = (size_t)(bm + row) * K + k0_ + ch * 8;                 \
            size_t gW = (size_t)(bn + row) * K + k0_ + ch * 8;                 \
            uint32_t hwo = (row * GP + ch * 8) * 2;                            \
            cp_async16(sb_ + ST_AHI * 2 + hwo, Ahi + gA);                      \
            cp_async16(sb_ + ST_ALO * 2 + hwo, Alo + gA);                      \
            cp_async16(sb_ + ST_WHI * 2 + hwo, Whi + gW);                      \
            cp_async16(sb_ + ST_WLO * 2 + hwo, Wlo + gW);                      \
        }                                                                      \
    } while (0)

    const int nch = K / 32;          // 64
    GEMM_ISSUE(0); CP_COMMIT();
    GEMM_ISSUE(1); CP_COMMIT();

    for (int c = 0; c < nch; c++) {
        if (c + 1 < nch) CP_WAIT1(); else CP_WAIT0();
        __syncthreads();
        if (c + 2 < nch) { GEMM_ISSUE(c + 2); CP_COMMIT(); }

        const uint32_t sb = sbase + ((c % 3) * STAGE_HW) * 2;
#pragma unroll
        for (int kk = 0; kk < 32; kk += 16) {
            uint32_t aHi[2][4], aLo[2][4], bHi[8][2], bLo[8][2];
#pragma unroll
            for (int mf = 0; mf < 2; mf++) {
                int hw = (wm * 32 + mf * 16 + a_row_in) * GP + kk + a_koff;
                ldsm_x4(aHi[mf], sb + (ST_AHI + hw) * 2);
                ldsm_x4(aLo[mf], sb + (ST_ALO + hw) * 2);
            }
#pragma unroll
            for (int p = 0; p < 4; p++) {
                int hw = (wn * 64 + p * 16 + b_row_in) * GP + kk + b_koff;
                uint32_t rh[4], rl[4];
                ldsm_x4(rh, sb + (ST_WHI + hw) * 2);
                ldsm_x4(rl, sb + (ST_WLO + hw) * 2);
                bHi[2 * p][0] = rh[0]; bHi[2 * p][1] = rh[1];
                bHi[2 * p + 1][0] = rh[2]; bHi[2 * p + 1][1] = rh[3];
                bLo[2 * p][0] = rl[0]; bLo[2 * p][1] = rl[1];
                bLo[2 * p + 1][0] = rl[2]; bLo[2 * p + 1][1] = rl[3];
            }
#pragma unroll
            for (int mf = 0; mf < 2; mf++)
#pragma unroll
                for (int nf = 0; nf < 8; nf++) {
                    mma16816(acc[mf][nf], aHi[mf], bHi[nf]);
                    mma16816(acc[mf][nf], aHi[mf], bLo[nf]);
                    mma16816(acc[mf][nf], aLo[mf], bHi[nf]);
                }
        }
    }

    const int gq = lane >> 2;
    const int qt = lane & 3;
#pragma unroll
    for (int mf = 0; mf < 2; mf++) {
#pragma unroll
        for (int nf = 0; nf < 8; nf++) {
            int row0 = bm + wm * 32 + mf * 16 + gq;
            int col  = bn + wn * 64 + nf * 8 + qt * 2;
            *(float2*)(Cout + (size_t)row0 * N + col) =
                make_float2(acc[mf][nf][0], acc[mf][nf][1]);
            *(float2*)(Cout + (size_t)(row0 + 8) * N + col) =
                make_float2(acc[mf][nf][2], acc[mf][nf][3]);
        }
    }
#undef GEMM_ISSUE
}

// Fused q/k/v projection: grid.x regions [0,16)=wq, [16,18)=wk, [18,20)=wv
__global__ __launch_bounds__(256)
void gemm_proj(const __nv_bfloat16* __restrict__ xh, const __nv_bfloat16* __restrict__ xl,
               const __nv_bfloat16* __restrict__ wqh, const __nv_bfloat16* __restrict__ wql,
               const __nv_bfloat16* __restrict__ wkh, const __nv_bfloat16* __restrict__ wkl,
               const __nv_bfloat16* __restrict__ wvh, const __nv_bfloat16* __restrict__ wvl,
               float* __restrict__ qraw, float* __restrict__ kraw, float* __restrict__ vraw)
{
    extern __shared__ __align__(16) uint16_t smem[];
    const int bx = blockIdx.x;
    const int bm = blockIdx.y * 128;
    const uint16_t *Whi, *Wlo;
    float* Cout;
    int N, bn;
    if (bx < 16)      { Whi = (const uint16_t*)wqh; Wlo = (const uint16_t*)wql;
                        Cout = qraw; N = H_ * D_;  bn = bx * 128; }
    else if (bx < 18) { Whi = (const uint16_t*)wkh; Wlo = (const uint16_t*)wkl;
                        Cout = kraw; N = HK_ * D_; bn = (bx - 16) * 128; }
    else              { Whi = (const uint16_t*)wvh; Wlo = (const uint16_t*)wvl;
                        Cout = vraw; N = HK_ * D_; bn = (bx - 18) * 128; }
    gemm_core((const uint16_t*)xh, (const uint16_t*)xl, Whi, Wlo, Cout, N, bm, bn, smem);
}

__global__ __launch_bounds__(256)
void gemm_out(const __nv_bfloat16* __restrict__ oh, const __nv_bfloat16* __restrict__ ol,
              const __nv_bfloat16* __restrict__ woh, const __nv_bfloat16* __restrict__ wol,
              float* __restrict__ out)
{
    extern __shared__ __align__(16) uint16_t smem[];
    gemm_core((const uint16_t*)oh, (const uint16_t*)ol,
              (const uint16_t*)woh, (const uint16_t*)wol,
              out, C_, blockIdx.y * 128, blockIdx.x * 128, smem);
}

// ===========================================================================
// RoPE + layout scatter, emitting fp32 (optional) AND bf16 hi/lo split
// ===========================================================================
__global__ void rope_scatter2(const float* __restrict__ raw,
                              const float* __restrict__ cosT,
                              const float* __restrict__ sinT,
                              float* __restrict__ dstF,
                              __nv_bfloat16* __restrict__ dstH,
                              __nv_bfloat16* __restrict__ dstL,
                              int heads, float scale, int doRope)
{
    const long long total = (long long)B_ * T_ * heads * (D_ / 2);
    long long p = (long long)blockIdx.x * blockDim.x + threadIdx.x;
    if (p >= total) return;

    const int n2 = heads * (D_ / 2);
    long long bt = p / n2;
    int r  = (int)(p % n2);
    int h  = r / (D_ / 2);
    int d  = (r % (D_ / 2)) * 2;
    int t  = (int)(bt % T_);
    int b  = (int)(bt / T_);

    const float* src = raw + bt * (size_t)(heads * D_) + h * D_ + d;
    float x1 = src[0];
    float x2 = src[1];
    float o1, o2;
    if (doRope) {
        float c1 = cosT[t * D_ + d],     s1 = sinT[t * D_ + d];
        float c2 = cosT[t * D_ + d + 1], s2 = sinT[t * D_ + d + 1];
        o1 = x1 * c1 - x2 * s1;
        o2 = x2 * c2 + x1 * s2;
    } else {
        o1 = x1; o2 = x2;
    }
    o1 *= scale; o2 *= scale;
    size_t oi = (((size_t)b * heads + h) * T_ + t) * D_ + d;
    if (dstF) { dstF[oi] = o1; dstF[oi + 1] = o2; }
    uint32_t hw, lw;
    split_pair(o1, o2, hw, lw);
    *(uint32_t*)((uint16_t*)dstH + oi) = hw;
    *(uint32_t*)((uint16_t*)dstL + oi) = lw;
}

// ===========================================================================
// Tensor-core causal flash attention v2: 128 q-rows/block, 256 threads
// (8 warps x 16 rows), double-buffered K/V, one sync per KV tile.
// ===========================================================================
#define FP 72
#define FSK_HI 0
#define FSK_LO 4608
#define FSV_HI 9216
#define FSV_LO 13824
#define FSTAGE 18432                     // hw per stage
#define FLASH_SMEM (2 * FSTAGE * 2)      // 73728 B

__global__ __launch_bounds__(256)
void flash_mma(const __nv_bfloat16* __restrict__ Qh, const __nv_bfloat16* __restrict__ Ql,
               const __nv_bfloat16* __restrict__ Kh, const __nv_bfloat16* __restrict__ Kl,
               const __nv_bfloat16* __restrict__ Vh, const __nv_bfloat16* __restrict__ Vl,
               __nv_bfloat16* __restrict__ Oh, __nv_bfloat16* __restrict__ Ol)
{
    extern __shared__ __align__(16) uint16_t buf[];

    const int qb  = blockIdx.x;          // 0..15 (128-row q block)
    const int bh  = blockIdx.y;
    const int b   = bh >> 5;
    const int h   = bh & 31;
    const int kh  = h >> 3;
    const int tid = threadIdx.x;
    const int wm  = tid >> 5;            // 0..7
    const int lane = tid & 31;
    const int gq  = lane >> 2;
    const int qt  = lane & 3;
    const int q0  = qb * 128;

    const uint16_t* Qhp = (const uint16_t*)Qh + ((size_t)bh * T_ + q0) * D_;
    const uint16_t* Qlp = (const uint16_t*)Ql + ((size_t)bh * T_ + q0) * D_;
    const size_t kvoff = ((size_t)(b * HK_ + kh) * T_) * D_;
    const uint16_t* Khp = (const uint16_t*)Kh + kvoff;
    const uint16_t* Klp = (const uint16_t*)Kl + kvoff;
    const uint16_t* Vhp = (const uint16_t*)Vh + kvoff;
    const uint16_t* Vlp = (const uint16_t*)Vl + kvoff;

    const uint32_t sbase = smem_u32(buf);

    // ---- stage Q (128x64 hi/lo) via cp.async into stage-0 buffer ----
    {
        int row = tid >> 1;              // 0..127
        int kc  = tid & 1;
#pragma unroll
        for (int g = 0; g < 4; g++) {
            int ch  = kc * 4 + g;
            size_t src = (size_t)row * D_ + ch * 8;
            uint32_t dsthw = row * FP + ch * 8;
            cp_async16(sbase + dsthw * 2, Qhp + src);
            cp_async16(sbase + (9216 + dsthw) * 2, Qlp + src);
        }
    }
    CP_COMMIT(); CP_WAIT0();
    __syncthreads();

    const int a_row = ((lane >> 3) & 1) * 8 + (lane & 7);
    const int a_k   = (lane >> 4) * 8;
    const int b_row = ((lane >> 4) & 1) * 8 + (lane & 7);
    const int b_k   = ((lane >> 3) & 1) * 8;

    uint32_t qhi[4][4], qlo[4][4];
#pragma unroll
    for (int dk = 0; dk < 4; dk++) {
        int hw = (wm * 16 + a_row) * FP + dk * 16 + a_k;
        ldsm_x4(qhi[dk], sbase + 2 * hw);
        ldsm_x4(qlo[dk], sbase + 2 * (9216 + hw));
    }
    __syncthreads();   // all warps done reading Q; buffer reusable

    float m0 = -1e30f, m1 = -1e30f, l0 = 0.f, l1 = 0.f;
    float o[8][4];
#pragma unroll
    for (int nf = 0; nf < 8; nf++)
#pragma unroll
        for (int q = 0; q < 4; q++) o[nf][q] = 0.f;

    const int nkb = 2 * qb + 2;          // KV tiles covering rows < q0+128
    const int wrow_lo = q0 + wm * 16;    // warp's lowest q row (global)

    // issue K (cp.async) + V (LDG/transpose STS) for tile kb into buf[kb&1]
#define FLASH_ISSUE(kb_) do {                                                  \
        uint32_t st_ = sbase + ((kb_) & 1) * FSTAGE * 2;                       \
        {                                                                      \
            int row_ = tid >> 2;                                               \
            int c0_  = (tid & 3) * 2;                                          \
            _Pragma("unroll")                                                  \
            for (int g_ = 0; g_ < 2; g_++) {                                   \
                int ch_ = c0_ + g_;                                            \
                size_t src_ = (size_t)((kb_) * 64 + row_) * D_ + ch_ * 8;      \
                uint32_t dhw_ = row_ * FP + ch_ * 8;                           \
                cp_async16(st_ + (FSK_HI + dhw_) * 2, Khp + src_);             \
                cp_async16(st_ + (FSK_LO + dhw_) * 2, Klp + src_);             \
            }                                                                  \
        }                                                                      \
        CP_COMMIT();                                                           \
        {                                                                      \
            int s0_ = 2 * (tid & 31);                                          \
            int d0_ = 8 * (tid >> 5);                                          \
            size_t g0_ = (size_t)((kb_) * 64 + s0_) * D_ + d0_;                \
            uint4 h0_ = *(const uint4*)(Vhp + g0_);                            \
            uint4 h1_ = *(const uint4*)(Vhp + g0_ + D_);                       \
            uint4 l0_ = *(const uint4*)(Vlp + g0_);                            \
            uint4 l1_ = *(const uint4*)(Vlp + g0_ + D_);                       \
            const uint32_t* a0_ = (const uint32_t*)&h0_;                       \
            const uint32_t* a1_ = (const uint32_t*)&h1_;                       \
            const uint32_t* c0p = (const uint32_t*)&l0_;                       \
            const uint32_t* c1p = (const uint32_t*)&l1_;                       \
            uint16_t* bb_ = buf + ((kb_) & 1) * FSTAGE;                        \
            _Pragma("unroll")                                                  \
            for (int j_ = 0; j_ < 4; j_++) {                                   \
                uint32_t ah_ = a0_[j_], bh_ = a1_[j_];                         \
                uint32_t al_ = c0p[j_], bl_ = c1p[j_];                         \
                int d_ = d0_ + 2 * j_;                                         \
                *(uint32_t*)&bb_[FSV_HI + d_ * FP + s0_] = (ah_ & 0xffffu) | (bh_ << 16); \
                *(uint32_t*)&bb_[FSV_HI + (d_ + 1) * FP + s0_] = (ah_ >> 16) | (bh_ & 0xffff0000u); \
                *(uint32_t*)&bb_[FSV_LO + d_ * FP + s0_] = (al_ & 0xffffu) | (bl_ << 16); \
                *(uint32_t*)&bb_[FSV_LO + (d_ + 1) * FP + s0_] = (al_ >> 16) | (bl_ & 0xffff0000u); \
            }                                                                  \
        }                                                                      \
    } while (0)

    FLASH_ISSUE(0);

    for (int kb = 0; kb < nkb; kb++) {
        CP_WAIT0();
        __syncthreads();                 // stage kb (K via cp.async, V via STS) visible
        if (kb + 1 < nkb) FLASH_ISSUE(kb + 1);

        // fully-masked warp: all its rows < first col of this tile
        if (64 * kb > wrow_lo + 15) continue;

        const uint32_t st = sbase + (kb & 1) * FSTAGE * 2;

        // ---- S = Q K^T (3-way split) ----
        float s[8][4];
#pragma unroll
        for (int nf = 0; nf < 8; nf++)
#pragma unroll
            for (int q = 0; q < 4; q++) s[nf][q] = 0.f;

#pragma unroll
        for (int dk = 0; dk < 4; dk++) {
            uint32_t kfh[4][4], kfl[4][4];
#pragma unroll
            for (int g = 0; g < 4; g++) {
                int hw = (16 * g + b_row) * FP + dk * 16 + b_k;
                ldsm_x4(kfh[g], st + 2 * (FSK_HI + hw));
                ldsm_x4(kfl[g], st + 2 * (FSK_LO + hw));
            }
#pragma unroll
            for (int g = 0; g < 4; g++) {
                mma16816(s[2 * g],     qhi[dk], &kfh[g][0]);
                mma16816(s[2 * g],     qhi[dk], &kfl[g][0]);
                mma16816(s[2 * g],     qlo[dk], &kfh[g][0]);
                mma16816(s[2 * g + 1], qhi[dk], &kfh[g][2]);
                mma16816(s[2 * g + 1], qhi[dk], &kfl[g][2]);
                mma16816(s[2 * g + 1], qlo[dk], &kfh[g][2]);
            }
        }

        // ---- causal mask (only when tile straddles the diagonal) ----
        if (64 * kb + 63 > wrow_lo) {
            int r0g = wrow_lo + gq;
            int r1g = r0g + 8;
#pragma unroll
            for (int nf = 0; nf < 8; nf++) {
                int c = 64 * kb + nf * 8 + 2 * qt;
                if (c     > r0g) s[nf][0] = -1e30f;
                if (c + 1 > r0g) s[nf][1] = -1e30f;
                if (c     > r1g) s[nf][2] = -1e30f;
                if (c + 1 > r1g) s[nf][3] = -1e30f;
            }
        }

        // ---- online softmax ----
        float mx0 = -1e30f, mx1 = -1e30f;
#pragma unroll
        for (int nf = 0; nf < 8; nf++) {
            mx0 = fmaxf(mx0, fmaxf(s[nf][0], s[nf][1]));
            mx1 = fmaxf(mx1, fmaxf(s[nf][2], s[nf][3]));
        }
        mx0 = fmaxf(mx0, __shfl_xor_sync(0xffffffffu, mx0, 1));
        mx0 = fmaxf(mx0, __shfl_xor_sync(0xffffffffu, mx0, 2));
        mx1 = fmaxf(mx1, __shfl_xor_sync(0xffffffffu, mx1, 1));
        mx1 = fmaxf(mx1, __shfl_xor_sync(0xffffffffu, mx1, 2));
        float mn0 = fmaxf(m0, mx0), mn1 = fmaxf(m1, mx1);
        float al0 = __expf(m0 - mn0), al1 = __expf(m1 - mn1);
        float sum0 = 0.f, sum1 = 0.f;
#pragma unroll
        for (int nf = 0; nf < 8; nf++) {
            s[nf][0] = __expf(s[nf][0] - mn0);
            s[nf][1] = __expf(s[nf][1] - mn0);
            s[nf][2] = __expf(s[nf][2] - mn1);
            s[nf][3] = __expf(s[nf][3] - mn1);
            sum0 += s[nf][0] + s[nf][1];
            sum1 += s[nf][2] + s[nf][3];
        }
        sum0 += __shfl_xor_sync(0xffffffffu, sum0, 1);
        sum0 += __shfl_xor_sync(0xffffffffu, sum0, 2);
        sum1 += __shfl_xor_sync(0xffffffffu, sum1, 1);
        sum1 += __shfl_xor_sync(0xffffffffu, sum1, 2);
        l0 = l0 * al0 + sum0;  m0 = mn0;
        l1 = l1 * al1 + sum1;  m1 = mn1;
#pragma unroll
        for (int nf = 0; nf < 8; nf++) {
            o[nf][0] *= al0; o[nf][1] *= al0;
            o[nf][2] *= al1; o[nf][3] *= al1;
        }

        // ---- pack P (hi/lo) ----
        uint32_t phi[4][4], plo[4][4];
#pragma unroll
        for (int kc = 0; kc < 4; kc++) {
            split_pair(s[2 * kc][0],     s[2 * kc][1],     phi[kc][0], plo[kc][0]);
            split_pair(s[2 * kc][2],     s[2 * kc][3],     phi[kc][1], plo[kc][1]);
            split_pair(s[2 * kc + 1][0], s[2 * kc + 1][1], phi[kc][2], plo[kc][2]);
            split_pair(s[2 * kc + 1][2], s[2 * kc + 1][3], phi[kc][3], plo[kc][3]);
        }

        // ---- O += P V (3-way split) ----
#pragma unroll
        for (int kc = 0; kc < 4; kc++) {
            uint32_t vfh[4][4], vfl[4][4];
#pragma unroll
            for (int g = 0; g < 4; g++) {
                int hw = (16 * g + b_row) * FP + kc * 16 + b_k;
                ldsm_x4(vfh[g], st + 2 * (FSV_HI + hw));
                ldsm_x4(vfl[g], st + 2 * (FSV_LO + hw));
            }
#pragma unroll
            for (int g = 0; g < 4; g++) {
                mma16816(o[2 * g],     phi[kc], &vfh[g][0]);
                mma16816(o[2 * g],     phi[kc], &vfl[g][0]);
                mma16816(o[2 * g],     plo[kc], &vfh[g][0]);
                mma16816(o[2 * g + 1], phi[kc], &vfh[g][2]);
                mma16816(o[2 * g + 1], phi[kc], &vfl[g][2]);
                mma16816(o[2 * g + 1], plo[kc], &vfh[g][2]);
            }
        }
    }
#undef FLASH_ISSUE

    // ---- epilogue: normalize + split + write bf16 hi/lo ----
    float inv0 = 1.0f / l0, inv1 = 1.0f / l1;
    int row0 = q0 + wm * 16 + gq;
    size_t base0 = ((size_t)b * T_ + row0) * (H_ * D_) + h * D_;
    size_t base1 = base0 + (size_t)8 * (H_ * D_);
    uint16_t* OhP = (uint16_t*)Oh;
    uint16_t* OlP = (uint16_t*)Ol;
#pragma unroll
    for (int nf = 0; nf < 8; nf++) {
        int c = nf * 8 + 2 * qt;
        uint32_t hw, lw;
        split_pair(o[nf][0] * inv0, o[nf][1] * inv0, hw, lw);
        *(uint32_t*)(OhP + base0 + c) = hw;
        *(uint32_t*)(OlP + base0 + c) = lw;
        split_pair(o[nf][2] * inv1, o[nf][3] * inv1, hw, lw);
        *(uint32_t*)(OhP + base1 + c) = hw;
        *(uint32_t*)(OlP + base1 + c) = lw;
    }
}

// ===========================================================================
extern "C" void kernel_launch(void* const* d_in, const int* in_sizes, int n_in,
                              void* d_out, int out_size)
{
    const float* x    = (const float*)d_in[0];
    const float* cosT = (const float*)d_in[1];
    const float* sinT = (const float*)d_in[2];
    const float* wq   = (const float*)d_in[3];
    const float* wk   = (const float*)d_in[4];
    const float* wv   = (const float*)d_in[5];
    const float* wo   = (const float*)d_in[6];

    float* out   = (float*)d_out;
    float* out_k = out   + (size_t)B_ * T_ * C_;
    float* out_v = out_k + (size_t)B_ * HK_ * T_ * D_;

    float *qraw, *kraw, *vraw;
    cudaGetSymbolAddress((void**)&qraw, g_qraw);
    cudaGetSymbolAddress((void**)&kraw, g_kraw);
    cudaGetSymbolAddress((void**)&vraw, g_vraw);

    __nv_bfloat16 *xh, *xl, *oh, *ol, *wqh, *wql, *wkh, *wkl, *wvh, *wvl, *woh, *wol;
    __nv_bfloat16 *qh, *ql, *kh, *kl, *vh, *vl;
    cudaGetSymbolAddress((void**)&xh, g_xh);   cudaGetSymbolAddress((void**)&xl, g_xl);
    cudaGetSymbolAddress((void**)&oh, g_oh);   cudaGetSymbolAddress((void**)&ol, g_ol);
    cudaGetSymbolAddress((void**)&wqh, g_wqh); cudaGetSymbolAddress((void**)&wql, g_wql);
    cudaGetSymbolAddress((void**)&wkh, g_wkh); cudaGetSymbolAddress((void**)&wkl, g_wkl);
    cudaGetSymbolAddress((void**)&wvh, g_wvh); cudaGetSymbolAddress((void**)&wvl, g_wvl);
    cudaGetSymbolAddress((void**)&woh, g_woh); cudaGetSymbolAddress((void**)&wol, g_wol);
    cudaGetSymbolAddress((void**)&qh, g_qh);   cudaGetSymbolAddress((void**)&ql, g_ql);
    cudaGetSymbolAddress((void**)&kh, g_kh);   cudaGetSymbolAddress((void**)&kl, g_kl);
    cudaGetSymbolAddress((void**)&vh, g_vh);   cudaGetSymbolAddress((void**)&vl, g_vl);

    cudaFuncSetAttribute(gemm_proj,
                         cudaFuncAttributeMaxDynamicSharedMemorySize, GEMM_SMEM);
    cudaFuncSetAttribute(gemm_out,
                         cudaFuncAttributeMaxDynamicSharedMemorySize, GEMM_SMEM);
    cudaFuncSetAttribute(flash_mma,
                         cudaFuncAttributeMaxDynamicSharedMemorySize, FLASH_SMEM);

    // ---- pre-split inputs into bf16 hi/lo ----
    {
        int nx = (MROWS * C_) / 8;
        int nw = ((H_ * D_) * C_) / 8;
        int ns = ((HK_ * D_) * C_) / 8;
        split_f32<<<(nx + 255) / 256, 256>>>(x,  xh,  xl,  nx);
        split_f32<<<(nw + 255) / 256, 256>>>(wq, wqh, wql, nw);
        split_f32<<<(ns + 255) / 256, 256>>>(wk, wkh, wkl, ns);
        split_f32<<<(ns + 255) / 256, 256>>>(wv, wvh, wvl, ns);
        split_f32<<<(nw + 255) / 256, 256>>>(wo, woh, wol, nw);
    }

    // ---- fused q/k/v projections ----
    gemm_proj<<<dim3(20, MROWS / 128), 256, GEMM_SMEM>>>(
        xh, xl, wqh, wql, wkh, wkl, wvh, wvl, qraw, kraw, vraw);

    // ---- RoPE + layout + split ----
    {
        long long pq = (long long)B_ * T_ * H_ * (D_ / 2);
        long long pk = (long long)B_ * T_ * HK_ * (D_ / 2);
        rope_scatter2<<<(unsigned)((pq + 255) / 256), 256>>>(
            qraw, cosT, sinT, (float*)nullptr, qh, ql, H_, 0.125f, 1);
        rope_scatter2<<<(unsigned)((pk + 255) / 256), 256>>>(
            kraw, cosT, sinT, out_k, kh, kl, HK_, 1.0f, 1);
        rope_scatter2<<<(unsigned)((pk + 255) / 256), 256>>>(
            vraw, cosT, sinT, out_v, vh, vl, HK_, 1.0f, 0);
    }

    // ---- flash attention (128-row q tiles) ----
    flash_mma<<<dim3(T_ / 128, B_ * H_), 256, FLASH_SMEM>>>(
        qh, ql, kh, kl, vh, vl, oh, ol);

    // ---- output projection ----
    gemm_out<<<dim3(C_ / 128, MROWS / 128), 256, GEMM_SMEM>>>(oh, ol, woh, wol, out);
}

// round 11
// speedup vs baseline: 1.0613x; 1.0613x over previous
#include <cuda_runtime.h>
#include <cuda_bf16.h>
#include <math.h>
#include <stdint.h>

// Problem constants
#define B_   2
#define T_   2048
#define C_   2048
#define H_   32
#define HK_  4
#define D_   64
#define MROWS (B_ * T_)          // 4096

// ---------------- scratch (static device globals; no allocation) ----------
__device__ float g_qraw[(long long)MROWS * (H_ * D_)];
__device__ float g_kraw[(long long)MROWS * (HK_ * D_)];
__device__ float g_vraw[(long long)MROWS * (HK_ * D_)];

__device__ __nv_bfloat16 g_xh[(long long)MROWS * C_],  g_xl[(long long)MROWS * C_];
__device__ __nv_bfloat16 g_oh[(long long)MROWS * C_],  g_ol[(long long)MROWS * C_];
__device__ __nv_bfloat16 g_wqh[(long long)(H_*D_) * C_],  g_wql[(long long)(H_*D_) * C_];
__device__ __nv_bfloat16 g_wkh[(long long)(HK_*D_) * C_], g_wkl[(long long)(HK_*D_) * C_];
__device__ __nv_bfloat16 g_wvh[(long long)(HK_*D_) * C_], g_wvl[(long long)(HK_*D_) * C_];
__device__ __nv_bfloat16 g_woh[(long long)C_ * (H_*D_)],  g_wol[(long long)C_ * (H_*D_)];
__device__ __nv_bfloat16 g_qh[(long long)B_*H_*T_*D_],  g_ql[(long long)B_*H_*T_*D_];
__device__ __nv_bfloat16 g_kh[(long long)B_*HK_*T_*D_], g_kl[(long long)B_*HK_*T_*D_];
__device__ __nv_bfloat16 g_vh[(long long)B_*HK_*T_*D_], g_vl[(long long)B_*HK_*T_*D_];

// ===========================================================================
// helpers
// ===========================================================================
__device__ __forceinline__ uint32_t smem_u32(const void* p) {
    uint32_t a;
    asm("{ .reg .u64 t; cvta.to.shared.u64 t, %1; cvt.u32.u64 %0, t; }"
        : "=r"(a) : "l"(p));
    return a;
}
__device__ __forceinline__ void ldsm_x4(uint32_t* r, uint32_t addr) {
    asm volatile("ldmatrix.sync.aligned.m8n8.x4.shared.b16 {%0,%1,%2,%3}, [%4];"
        : "=r"(r[0]), "=r"(r[1]), "=r"(r[2]), "=r"(r[3]) : "r"(addr));
}
__device__ __forceinline__ void mma16816(float* c, const uint32_t* a, const uint32_t* b) {
    asm volatile(
        "mma.sync.aligned.m16n8k16.row.col.f32.bf16.bf16.f32 "
        "{%0,%1,%2,%3}, {%4,%5,%6,%7}, {%8,%9}, {%0,%1,%2,%3};"
        : "+f"(c[0]), "+f"(c[1]), "+f"(c[2]), "+f"(c[3])
        : "r"(a[0]), "r"(a[1]), "r"(a[2]), "r"(a[3]), "r"(b[0]), "r"(b[1]));
}
__device__ __forceinline__ void split_pair(float a, float b, uint32_t& hi, uint32_t& lo) {
    __nv_bfloat162 h = __floats2bfloat162_rn(a, b);
    float ra = a - __bfloat162float(h.x);
    float rb = b - __bfloat162float(h.y);
    __nv_bfloat162 l = __floats2bfloat162_rn(ra, rb);
    hi = *(uint32_t*)&h;
    lo = *(uint32_t*)&l;
}
__device__ __forceinline__ void cp_async16(uint32_t dst, const void* src) {
    asm volatile("cp.async.cg.shared.global [%0], [%1], 16;" :: "r"(dst), "l"(src));
}
#define CP_COMMIT() asm volatile("cp.async.commit_group;" ::: "memory")
#define CP_WAIT1()  asm volatile("cp.async.wait_group 1;" ::: "memory")
#define CP_WAIT0()  asm volatile("cp.async.wait_group 0;" ::: "memory")

// ===========================================================================
// fp32 -> bf16 hi/lo global split
// ===========================================================================
__global__ void split_f32(const float* __restrict__ src,
                          __nv_bfloat16* __restrict__ hi,
                          __nv_bfloat16* __restrict__ lo, int n8)
{
    int i = blockIdx.x * blockDim.x + threadIdx.x;
    if (i >= n8) return;
    const float4* p = (const float4*)src + 2 * (size_t)i;
    float4 f0 = p[0], f1 = p[1];
    uint4 h, l;
    split_pair(f0.x, f0.y, h.x, l.x);
    split_pair(f0.z, f0.w, h.y, l.y);
    split_pair(f1.x, f1.y, h.z, l.z);
    split_pair(f1.z, f1.w, h.w, l.w);
    ((uint4*)hi)[i] = h;
    ((uint4*)lo)[i] = l;
}

// ===========================================================================
// GEMM core (R9 known-good): 128x128 block, bf16x3, K=2048, 2-stage cp.async.
// 256 threads = 8 warps (4m x 2n), warp tile 32x64.
// ===========================================================================
#define GP 40
#define ST_AHI 0
#define ST_ALO (128 * GP)
#define ST_WHI (2 * 128 * GP)
#define ST_WLO (3 * 128 * GP)
#define STAGE_HW (4 * 128 * GP)          // 20480 hw = 40960 B
#define GEMM_SMEM (2 * STAGE_HW * 2)     // 81920 B

__device__ __forceinline__ void gemm_core(
    const uint16_t* __restrict__ Ahi, const uint16_t* __restrict__ Alo,
    const uint16_t* __restrict__ Whi, const uint16_t* __restrict__ Wlo,
    float* __restrict__ Cout, int N, int bm, int bn, uint16_t* smem)
{
    const int K = C_;
    const uint32_t sbase = smem_u32(smem);
    const int tid  = threadIdx.x;
    const int wid  = tid >> 5;
    const int lane = tid & 31;
    const int wm   = wid & 3;
    const int wn   = wid >> 2;

    float acc[2][8][4];
#pragma unroll
    for (int i = 0; i < 2; i++)
#pragma unroll
        for (int j = 0; j < 8; j++)
#pragma unroll
            for (int q = 0; q < 4; q++) acc[i][j][q] = 0.f;

    const int a_row_in = ((lane >> 3) & 1) * 8 + (lane & 7);
    const int a_koff   = (lane >> 4) * 8;
    const int b_row_in = ((lane >> 4) & 1) * 8 + (lane & 7);
    const int b_koff   = ((lane >> 3) & 1) * 8;

#define GEMM_ISSUE(c) do {                                                    \
        int k0_ = (c) * 32;                                                   \
        uint32_t sb_ = sbase + (((c) & 1) * STAGE_HW) * 2;                     \
        _Pragma("unroll")                                                      \
        for (int r_ = 0; r_ < 2; r_++) {                                      \
            int e_  = tid + r_ * 256;                                          \
            int row = e_ >> 2;                                                 \
            int ch  = e_ & 3;                                                  \
            size_t gA = (size_t)(bm + row) * K + k0_ + ch * 8;                 \
            size_t gW = (size_t)(bn + row) * K + k0_ + ch * 8;                 \
            uint32_t hwo = (row * GP + ch * 8) * 2;                            \
            cp_async16(sb_ + ST_AHI * 2 + hwo, Ahi + gA);                      \
            cp_async16(sb_ + ST_ALO * 2 + hwo, Alo + gA);                      \
            cp_async16(sb_ + ST_WHI * 2 + hwo, Whi + gW);                      \
            cp_async16(sb_ + ST_WLO * 2 + hwo, Wlo + gW);                      \
        }                                                                      \
    } while (0)

    GEMM_ISSUE(0); CP_COMMIT();

    const int nch = K / 32;
    for (int c = 0; c < nch; c++) {
        if (c + 1 < nch) { GEMM_ISSUE(c + 1); CP_COMMIT(); CP_WAIT1(); }
        else             { CP_WAIT0(); }
        __syncthreads();

        const uint32_t sb = sbase + ((c & 1) * STAGE_HW) * 2;
#pragma unroll
        for (int kk = 0; kk < 32; kk += 16) {
            uint32_t aHi[2][4], aLo[2][4], bHi[8][2], bLo[8][2];
#pragma unroll
            for (int mf = 0; mf < 2; mf++) {
                int hw = (wm * 32 + mf * 16 + a_row_in) * GP + kk + a_koff;
                ldsm_x4(aHi[mf], sb + (ST_AHI + hw) * 2);
                ldsm_x4(aLo[mf], sb + (ST_ALO + hw) * 2);
            }
#pragma unroll
            for (int p = 0; p < 4; p++) {
                int hw = (wn * 64 + p * 16 + b_row_in) * GP + kk + b_koff;
                uint32_t rh[4], rl[4];
                ldsm_x4(rh, sb + (ST_WHI + hw) * 2);
                ldsm_x4(rl, sb + (ST_WLO + hw) * 2);
                bHi[2 * p][0] = rh[0]; bHi[2 * p][1] = rh[1];
                bHi[2 * p + 1][0] = rh[2]; bHi[2 * p + 1][1] = rh[3];
                bLo[2 * p][0] = rl[0]; bLo[2 * p][1] = rl[1];
                bLo[2 * p + 1][0] = rl[2]; bLo[2 * p + 1][1] = rl[3];
            }
#pragma unroll
            for (int mf = 0; mf < 2; mf++)
#pragma unroll
                for (int nf = 0; nf < 8; nf++) {
                    mma16816(acc[mf][nf], aHi[mf], bHi[nf]);
                    mma16816(acc[mf][nf], aHi[mf], bLo[nf]);
                    mma16816(acc[mf][nf], aLo[mf], bHi[nf]);
                }
        }
        __syncthreads();
    }

    const int gq = lane >> 2;
    const int qt = lane & 3;
#pragma unroll
    for (int mf = 0; mf < 2; mf++) {
#pragma unroll
        for (int nf = 0; nf < 8; nf++) {
            int row0 = bm + wm * 32 + mf * 16 + gq;
            int col  = bn + wn * 64 + nf * 8 + qt * 2;
            *(float2*)(Cout + (size_t)row0 * N + col) =
                make_float2(acc[mf][nf][0], acc[mf][nf][1]);
            *(float2*)(Cout + (size_t)(row0 + 8) * N + col) =
                make_float2(acc[mf][nf][2], acc[mf][nf][3]);
        }
    }
#undef GEMM_ISSUE
}

// Fused q/k/v projection: grid.x regions [0,16)=wq, [16,18)=wk, [18,20)=wv
__global__ __launch_bounds__(256)
void gemm_proj(const __nv_bfloat16* __restrict__ xh, const __nv_bfloat16* __restrict__ xl,
               const __nv_bfloat16* __restrict__ wqh, const __nv_bfloat16* __restrict__ wql,
               const __nv_bfloat16* __restrict__ wkh, const __nv_bfloat16* __restrict__ wkl,
               const __nv_bfloat16* __restrict__ wvh, const __nv_bfloat16* __restrict__ wvl,
               float* __restrict__ qraw, float* __restrict__ kraw, float* __restrict__ vraw)
{
    extern __shared__ __align__(16) uint16_t smem[];
    const int bx = blockIdx.x;
    const int bm = blockIdx.y * 128;
    const uint16_t *Whi, *Wlo;
    float* Cout;
    int N, bn;
    if (bx < 16)      { Whi = (const uint16_t*)wqh; Wlo = (const uint16_t*)wql;
                        Cout = qraw; N = H_ * D_;  bn = bx * 128; }
    else if (bx < 18) { Whi = (const uint16_t*)wkh; Wlo = (const uint16_t*)wkl;
                        Cout = kraw; N = HK_ * D_; bn = (bx - 16) * 128; }
    else              { Whi = (const uint16_t*)wvh; Wlo = (const uint16_t*)wvl;
                        Cout = vraw; N = HK_ * D_; bn = (bx - 18) * 128; }
    gemm_core((const uint16_t*)xh, (const uint16_t*)xl, Whi, Wlo, Cout, N, bm, bn, smem);
}

__global__ __launch_bounds__(256)
void gemm_out(const __nv_bfloat16* __restrict__ oh, const __nv_bfloat16* __restrict__ ol,
              const __nv_bfloat16* __restrict__ woh, const __nv_bfloat16* __restrict__ wol,
              float* __restrict__ out)
{
    extern __shared__ __align__(16) uint16_t smem[];
    gemm_core((const uint16_t*)oh, (const uint16_t*)ol,
              (const uint16_t*)woh, (const uint16_t*)wol,
              out, C_, blockIdx.y * 128, blockIdx.x * 128, smem);
}

// ===========================================================================
// RoPE + layout scatter, emitting fp32 (optional) AND bf16 hi/lo split
// ===========================================================================
__global__ void rope_scatter2(const float* __restrict__ raw,
                              const float* __restrict__ cosT,
                              const float* __restrict__ sinT,
                              float* __restrict__ dstF,
                              __nv_bfloat16* __restrict__ dstH,
                              __nv_bfloat16* __restrict__ dstL,
                              int heads, float scale, int doRope)
{
    const long long total = (long long)B_ * T_ * heads * (D_ / 2);
    long long p = (long long)blockIdx.x * blockDim.x + threadIdx.x;
    if (p >= total) return;

    const int n2 = heads * (D_ / 2);
    long long bt = p / n2;
    int r  = (int)(p % n2);
    int h  = r / (D_ / 2);
    int d  = (r % (D_ / 2)) * 2;
    int t  = (int)(bt % T_);
    int b  = (int)(bt / T_);

    const float* src = raw + bt * (size_t)(heads * D_) + h * D_ + d;
    float x1 = src[0];
    float x2 = src[1];
    float o1, o2;
    if (doRope) {
        float c1 = cosT[t * D_ + d],     s1 = sinT[t * D_ + d];
        float c2 = cosT[t * D_ + d + 1], s2 = sinT[t * D_ + d + 1];
        o1 = x1 * c1 - x2 * s1;
        o2 = x2 * c2 + x1 * s2;
    } else {
        o1 = x1; o2 = x2;
    }
    o1 *= scale; o2 *= scale;
    size_t oi = (((size_t)b * heads + h) * T_ + t) * D_ + d;
    if (dstF) { dstF[oi] = o1; dstF[oi + 1] = o2; }
    uint32_t hw, lw;
    split_pair(o1, o2, hw, lw);
    *(uint32_t*)((uint16_t*)dstH + oi) = hw;
    *(uint32_t*)((uint16_t*)dstL + oi) = lw;
}

// ===========================================================================
// Tensor-core causal flash attention (GQA): Br=64, 128 threads (4 warps),
// double-buffered K/V stages, ONE sync per KV tile, loads overlap compute.
// ===========================================================================
#define FP 72
#define FSK_HI 0
#define FSK_LO 4608
#define FSV_HI 9216
#define FSV_LO 13824
#define FSTAGE 18432                     // hw per stage
#define FLASH_SMEM (2 * FSTAGE * 2)      // 73728 B

__global__ __launch_bounds__(128)
void flash_mma(const __nv_bfloat16* __restrict__ Qh, const __nv_bfloat16* __restrict__ Ql,
               const __nv_bfloat16* __restrict__ Kh, const __nv_bfloat16* __restrict__ Kl,
               const __nv_bfloat16* __restrict__ Vh, const __nv_bfloat16* __restrict__ Vl,
               __nv_bfloat16* __restrict__ Oh, __nv_bfloat16* __restrict__ Ol)
{
    extern __shared__ __align__(16) uint16_t buf[];

    const int qb  = blockIdx.x;
    const int bh  = blockIdx.y;
    const int b   = bh >> 5;
    const int h   = bh & 31;
    const int kh  = h >> 3;
    const int tid = threadIdx.x;
    const int wm  = tid >> 5;
    const int lane = tid & 31;
    const int gq  = lane >> 2;
    const int qt  = lane & 3;
    const int q0  = qb * 64;

    const uint16_t* Qhp = (const uint16_t*)Qh + ((size_t)bh * T_ + q0) * D_;
    const uint16_t* Qlp = (const uint16_t*)Ql + ((size_t)bh * T_ + q0) * D_;
    const size_t kvoff = ((size_t)(b * HK_ + kh) * T_) * D_;
    const uint16_t* Khp = (const uint16_t*)Kh + kvoff;
    const uint16_t* Klp = (const uint16_t*)Kl + kvoff;
    const uint16_t* Vhp = (const uint16_t*)Vh + kvoff;
    const uint16_t* Vlp = (const uint16_t*)Vl + kvoff;

    const uint32_t sbase = smem_u32(buf);

    // ---- stage Q (64x64 hi/lo) via cp.async into stage 0 ----
    {
        int row = tid >> 1;
        int kc  = tid & 1;
#pragma unroll
        for (int g = 0; g < 4; g++) {
            int ch  = kc * 4 + g;
            size_t src = (size_t)row * D_ + ch * 8;
            uint32_t dsthw = row * FP + ch * 8;
            cp_async16(sbase + (FSK_HI + dsthw) * 2, Qhp + src);
            cp_async16(sbase + (FSK_LO + dsthw) * 2, Qlp + src);
        }
    }
    CP_COMMIT(); CP_WAIT0();
    __syncthreads();

    const int a_row = ((lane >> 3) & 1) * 8 + (lane & 7);
    const int a_k   = (lane >> 4) * 8;
    const int b_row = ((lane >> 4) & 1) * 8 + (lane & 7);
    const int b_k   = ((lane >> 3) & 1) * 8;

    uint32_t qhi[4][4], qlo[4][4];
#pragma unroll
    for (int dk = 0; dk < 4; dk++) {
        int hw = (wm * 16 + a_row) * FP + dk * 16 + a_k;
        ldsm_x4(qhi[dk], sbase + 2 * (FSK_HI + hw));
        ldsm_x4(qlo[dk], sbase + 2 * (FSK_LO + hw));
    }
    __syncthreads();   // Q reads done; stage 0 reusable

    float m0 = -1e30f, m1 = -1e30f, l0 = 0.f, l1 = 0.f;
    float o[8][4];
#pragma unroll
    for (int nf = 0; nf < 8; nf++)
#pragma unroll
        for (int q = 0; q < 4; q++) o[nf][q] = 0.f;

    // issue K (cp.async) + V (LDG/transpose STS) for tile kb_ into stage kb_&1
#define FLASH_ISSUE(kb_) do {                                                  \
        uint32_t st_ = sbase + ((kb_) & 1) * FSTAGE * 2;                       \
        uint16_t* bb_ = buf + ((kb_) & 1) * FSTAGE;                            \
        {                                                                      \
            int row_ = tid >> 1;                                               \
            int kc_  = tid & 1;                                                \
            _Pragma("unroll")                                                  \
            for (int g_ = 0; g_ < 4; g_++) {                                   \
                int ch_ = kc_ * 4 + g_;                                        \
                size_t src_ = (size_t)((kb_) * 64 + row_) * D_ + ch_ * 8;      \
                uint32_t dhw_ = row_ * FP + ch_ * 8;                           \
                cp_async16(st_ + (FSK_HI + dhw_) * 2, Khp + src_);             \
                cp_async16(st_ + (FSK_LO + dhw_) * 2, Klp + src_);             \
            }                                                                  \
        }                                                                      \
        CP_COMMIT();                                                           \
        _Pragma("unroll")                                                      \
        for (int u2_ = 0; u2_ < 2; u2_++) {                                    \
            int u_  = tid + u2_ * 128;                                         \
            int s0_ = 2 * (u_ & 31);                                           \
            int d0_ = 8 * (u_ >> 5);                                           \
            size_t g0_ = (size_t)((kb_) * 64 + s0_) * D_ + d0_;                \
            uint4 h0_ = *(const uint4*)(Vhp + g0_);                            \
            uint4 h1_ = *(const uint4*)(Vhp + g0_ + D_);                       \
            uint4 l0_ = *(const uint4*)(Vlp + g0_);                            \
            uint4 l1_ = *(const uint4*)(Vlp + g0_ + D_);                       \
            const uint32_t* a0_ = (const uint32_t*)&h0_;                       \
            const uint32_t* a1_ = (const uint32_t*)&h1_;                       \
            const uint32_t* c0_ = (const uint32_t*)&l0_;                       \
            const uint32_t* c1_ = (const uint32_t*)&l1_;                       \
            _Pragma("unroll")                                                  \
            for (int j_ = 0; j_ < 4; j_++) {                                   \
                uint32_t ah_ = a0_[j_], bh_ = a1_[j_];                         \
                uint32_t al_ = c0_[j_], bl_ = c1_[j_];                         \
                int d_ = d0_ + 2 * j_;                                         \
                *(uint32_t*)&bb_[FSV_HI + d_ * FP + s0_] = (ah_ & 0xffffu) | (bh_ << 16); \
                *(uint32_t*)&bb_[FSV_HI + (d_ + 1) * FP + s0_] = (ah_ >> 16) | (bh_ & 0xffff0000u); \
                *(uint32_t*)&bb_[FSV_LO + d_ * FP + s0_] = (al_ & 0xffffu) | (bl_ << 16); \
                *(uint32_t*)&bb_[FSV_LO + (d_ + 1) * FP + s0_] = (al_ >> 16) | (bl_ & 0xffff0000u); \
            }                                                                  \
        }                                                                      \
    } while (0)

    FLASH_ISSUE(0);

    for (int kb = 0; kb <= qb; kb++) {
        CP_WAIT0();
        __syncthreads();                 // stage kb visible (K cp.async + V STS)
        if (kb + 1 <= qb) FLASH_ISSUE(kb + 1);

        const uint32_t st = sbase + (kb & 1) * FSTAGE * 2;

        // ---- S = Q K^T (3-way split) ----
        float s[8][4];
#pragma unroll
        for (int nf = 0; nf < 8; nf++)
#pragma unroll
            for (int q = 0; q < 4; q++) s[nf][q] = 0.f;

#pragma unroll
        for (int dk = 0; dk < 4; dk++) {
            uint32_t kfh[4][4], kfl[4][4];
#pragma unroll
            for (int g = 0; g < 4; g++) {
                int hw = (16 * g + b_row) * FP + dk * 16 + b_k;
                ldsm_x4(kfh[g], st + 2 * (FSK_HI + hw));
                ldsm_x4(kfl[g], st + 2 * (FSK_LO + hw));
            }
#pragma unroll
            for (int g = 0; g < 4; g++) {
                mma16816(s[2 * g],     qhi[dk], &kfh[g][0]);
                mma16816(s[2 * g],     qhi[dk], &kfl[g][0]);
                mma16816(s[2 * g],     qlo[dk], &kfh[g][0]);
                mma16816(s[2 * g + 1], qhi[dk], &kfh[g][2]);
                mma16816(s[2 * g + 1], qhi[dk], &kfl[g][2]);
                mma16816(s[2 * g + 1], qlo[dk], &kfh[g][2]);
            }
        }

        // ---- causal mask on diagonal block ----
        if (kb == qb) {
            int r0g = 16 * wm + gq;
            int r1g = r0g + 8;
#pragma unroll
            for (int nf = 0; nf < 8; nf++) {
                int c = nf * 8 + 2 * qt;
                if (c     > r0g) s[nf][0] = -1e30f;
                if (c + 1 > r0g) s[nf][1] = -1e30f;
                if (c     > r1g) s[nf][2] = -1e30f;
                if (c + 1 > r1g) s[nf][3] = -1e30f;
            }
        }

        // ---- online softmax ----
        float mx0 = -1e30f, mx1 = -1e30f;
#pragma unroll
        for (int nf = 0; nf < 8; nf++) {
            mx0 = fmaxf(mx0, fmaxf(s[nf][0], s[nf][1]));
            mx1 = fmaxf(mx1, fmaxf(s[nf][2], s[nf][3]));
        }
        mx0 = fmaxf(mx0, __shfl_xor_sync(0xffffffffu, mx0, 1));
        mx0 = fmaxf(mx0, __shfl_xor_sync(0xffffffffu, mx0, 2));
        mx1 = fmaxf(mx1, __shfl_xor_sync(0xffffffffu, mx1, 1));
        mx1 = fmaxf(mx1, __shfl_xor_sync(0xffffffffu, mx1, 2));
        float mn0 = fmaxf(m0, mx0), mn1 = fmaxf(m1, mx1);
        float al0 = __expf(m0 - mn0), al1 = __expf(m1 - mn1);
        float sum0 = 0.f, sum1 = 0.f;
#pragma unroll
        for (int nf = 0; nf < 8; nf++) {
            s[nf][0] = __expf(s[nf][0] - mn0);
            s[nf][1] = __expf(s[nf][1] - mn0);
            s[nf][2] = __expf(s[nf][2] - mn1);
            s[nf][3] = __expf(s[nf][3] - mn1);
            sum0 += s[nf][0] + s[nf][1];
            sum1 += s[nf][2] + s[nf][3];
        }
        sum0 += __shfl_xor_sync(0xffffffffu, sum0, 1);
        sum0 += __shfl_xor_sync(0xffffffffu, sum0, 2);
        sum1 += __shfl_xor_sync(0xffffffffu, sum1, 1);
        sum1 += __shfl_xor_sync(0xffffffffu, sum1, 2);
        l0 = l0 * al0 + sum0;  m0 = mn0;
        l1 = l1 * al1 + sum1;  m1 = mn1;
#pragma unroll
        for (int nf = 0; nf < 8; nf++) {
            o[nf][0] *= al0; o[nf][1] *= al0;
            o[nf][2] *= al1; o[nf][3] *= al1;
        }

        // ---- pack P (hi/lo) ----
        uint32_t phi[4][4], plo[4][4];
#pragma unroll
        for (int kc = 0; kc < 4; kc++) {
            split_pair(s[2 * kc][0],     s[2 * kc][1],     phi[kc][0], plo[kc][0]);
            split_pair(s[2 * kc][2],     s[2 * kc][3],     phi[kc][1], plo[kc][1]);
            split_pair(s[2 * kc + 1][0], s[2 * kc + 1][1], phi[kc][2], plo[kc][2]);
            split_pair(s[2 * kc + 1][2], s[2 * kc + 1][3], phi[kc][3], plo[kc][3]);
        }

        // ---- O += P V (3-way split) ----
#pragma unroll
        for (int kc = 0; kc < 4; kc++) {
            uint32_t vfh[4][4], vfl[4][4];
#pragma unroll
            for (int g = 0; g < 4; g++) {
                int hw = (16 * g + b_row) * FP + kc * 16 + b_k;
                ldsm_x4(vfh[g], st + 2 * (FSV_HI + hw));
                ldsm_x4(vfl[g], st + 2 * (FSV_LO + hw));
            }
#pragma unroll
            for (int g = 0; g < 4; g++) {
                mma16816(o[2 * g],     phi[kc], &vfh[g][0]);
                mma16816(o[2 * g],     phi[kc], &vfl[g][0]);
                mma16816(o[2 * g],     plo[kc], &vfh[g][0]);
                mma16816(o[2 * g + 1], phi[kc], &vfh[g][2]);
                mma16816(o[2 * g + 1], phi[kc], &vfl[g][2]);
                mma16816(o[2 * g + 1], plo[kc], &vfh[g][2]);
            }
        }
    }
#undef FLASH_ISSUE

    // ---- epilogue: normalize + split + write bf16 hi/lo ----
    float inv0 = 1.0f / l0, inv1 = 1.0f / l1;
    int row0 = q0 + wm * 16 + gq;
    size_t base0 = ((size_t)b * T_ + row0) * (H_ * D_) + h * D_;
    size_t base1 = base0 + (size_t)8 * (H_ * D_);
    uint16_t* OhP = (uint16_t*)Oh;
    uint16_t* OlP = (uint16_t*)Ol;
#pragma unroll
    for (int nf = 0; nf < 8; nf++) {
        int c = nf * 8 + 2 * qt;
        uint32_t hw, lw;
        split_pair(o[nf][0] * inv0, o[nf][1] * inv0, hw, lw);
        *(uint32_t*)(OhP + base0 + c) = hw;
        *(uint32_t*)(OlP + base0 + c) = lw;
        split_pair(o[nf][2] * inv1, o[nf][3] * inv1, hw, lw);
        *(uint32_t*)(OhP + base1 + c) = hw;
        *(uint32_t*)(OlP + base1 + c) = lw;
    }
}

// ===========================================================================
extern "C" void kernel_launch(void* const* d_in, const int* in_sizes, int n_in,
                              void* d_out, int out_size)
{
    const float* x    = (const float*)d_in[0];
    const float* cosT = (const float*)d_in[1];
    const float* sinT = (const float*)d_in[2];
    const float* wq   = (const float*)d_in[3];
    const float* wk   = (const float*)d_in[4];
    const float* wv   = (const float*)d_in[5];
    const float* wo   = (const float*)d_in[6];

    float* out   = (float*)d_out;
    float* out_k = out   + (size_t)B_ * T_ * C_;
    float* out_v = out_k + (size_t)B_ * HK_ * T_ * D_;

    float *qraw, *kraw, *vraw;
    cudaGetSymbolAddress((void**)&qraw, g_qraw);
    cudaGetSymbolAddress((void**)&kraw, g_kraw);
    cudaGetSymbolAddress((void**)&vraw, g_vraw);

    __nv_bfloat16 *xh, *xl, *oh, *ol, *wqh, *wql, *wkh, *wkl, *wvh, *wvl, *woh, *wol;
    __nv_bfloat16 *qh, *ql, *kh, *kl, *vh, *vl;
    cudaGetSymbolAddress((void**)&xh, g_xh);   cudaGetSymbolAddress((void**)&xl, g_xl);
    cudaGetSymbolAddress((void**)&oh, g_oh);   cudaGetSymbolAddress((void**)&ol, g_ol);
    cudaGetSymbolAddress((void**)&wqh, g_wqh); cudaGetSymbolAddress((void**)&wql, g_wql);
    cudaGetSymbolAddress((void**)&wkh, g_wkh); cudaGetSymbolAddress((void**)&wkl, g_wkl);
    cudaGetSymbolAddress((void**)&wvh, g_wvh); cudaGetSymbolAddress((void**)&wvl, g_wvl);
    cudaGetSymbolAddress((void**)&woh, g_woh); cudaGetSymbolAddress((void**)&wol, g_wol);
    cudaGetSymbolAddress((void**)&qh, g_qh);   cudaGetSymbolAddress((void**)&ql, g_ql);
    cudaGetSymbolAddress((void**)&kh, g_kh);   cudaGetSymbolAddress((void**)&kl, g_kl);
    cudaGetSymbolAddress((void**)&vh, g_vh);   cudaGetSymbolAddress((void**)&vl, g_vl);

    cudaFuncSetAttribute(gemm_proj,
                         cudaFuncAttributeMaxDynamicSharedMemorySize, GEMM_SMEM);
    cudaFuncSetAttribute(gemm_out,
                         cudaFuncAttributeMaxDynamicSharedMemorySize, GEMM_SMEM);
    cudaFuncSetAttribute(flash_mma,
                         cudaFuncAttributeMaxDynamicSharedMemorySize, FLASH_SMEM);

    // ---- pre-split inputs into bf16 hi/lo ----
    {
        int nx = (MROWS * C_) / 8;
        int nw = ((H_ * D_) * C_) / 8;
        int ns = ((HK_ * D_) * C_) / 8;
        split_f32<<<(nx + 255) / 256, 256>>>(x,  xh,  xl,  nx);
        split_f32<<<(nw + 255) / 256, 256>>>(wq, wqh, wql, nw);
        split_f32<<<(ns + 255) / 256, 256>>>(wk, wkh, wkl, ns);
        split_f32<<<(ns + 255) / 256, 256>>>(wv, wvh, wvl, ns);
        split_f32<<<(nw + 255) / 256, 256>>>(wo, woh, wol, nw);
    }

    // ---- fused q/k/v projections ----
    gemm_proj<<<dim3(20, MROWS / 128), 256, GEMM_SMEM>>>(
        xh, xl, wqh, wql, wkh, wkl, wvh, wvl, qraw, kraw, vraw);

    // ---- RoPE + layout + split ----
    {
        long long pq = (long long)B_ * T_ * H_ * (D_ / 2);
        long long pk = (long long)B_ * T_ * HK_ * (D_ / 2);
        rope_scatter2<<<(unsigned)((pq + 255) / 256), 256>>>(
            qraw, cosT, sinT, (float*)nullptr, qh, ql, H_, 0.125f, 1);
        rope_scatter2<<<(unsigned)((pk + 255) / 256), 256>>>(
            kraw, cosT, sinT, out_k, kh, kl, HK_, 1.0f, 1);
        rope_scatter2<<<(unsigned)((pk + 255) / 256), 256>>>(
            vraw, cosT, sinT, out_v, vh, vl, HK_, 1.0f, 0);
    }

    // ---- flash attention (double-buffered K/V, one sync per tile) ----
    flash_mma<<<dim3(T_ / 64, B_ * H_), 128, FLASH_SMEM>>>(
        qh, ql, kh, kl, vh, vl, oh, ol);

    // ---- output projection ----
    gemm_out<<<dim3(C_ / 128, MROWS / 128), 256, GEMM_SMEM>>>(oh, ol, woh, wol, out);
}

// round 12
// speedup vs baseline: 1.0749x; 1.0128x over previous
#include <cuda_runtime.h>
#include <cuda_bf16.h>
#include <math.h>
#include <stdint.h>

// Problem constants
#define B_   2
#define T_   2048
#define C_   2048
#define H_   32
#define HK_  4
#define D_   64
#define MROWS (B_ * T_)          // 4096

// ---------------- scratch (static device globals; no allocation) ----------
__device__ __nv_bfloat16 g_xh[(long long)MROWS * C_],  g_xl[(long long)MROWS * C_];
__device__ __nv_bfloat16 g_oh[(long long)MROWS * C_],  g_ol[(long long)MROWS * C_];
__device__ __nv_bfloat16 g_wqh[(long long)(H_*D_) * C_],  g_wql[(long long)(H_*D_) * C_];
__device__ __nv_bfloat16 g_wkh[(long long)(HK_*D_) * C_], g_wkl[(long long)(HK_*D_) * C_];
__device__ __nv_bfloat16 g_wvh[(long long)(HK_*D_) * C_], g_wvl[(long long)(HK_*D_) * C_];
__device__ __nv_bfloat16 g_woh[(long long)C_ * (H_*D_)],  g_wol[(long long)C_ * (H_*D_)];
__device__ __nv_bfloat16 g_qh[(long long)B_*H_*T_*D_],  g_ql[(long long)B_*H_*T_*D_];
__device__ __nv_bfloat16 g_kh[(long long)B_*HK_*T_*D_], g_kl[(long long)B_*HK_*T_*D_];
__device__ __nv_bfloat16 g_vh[(long long)B_*HK_*T_*D_], g_vl[(long long)B_*HK_*T_*D_];

// ===========================================================================
// helpers
// ===========================================================================
__device__ __forceinline__ uint32_t smem_u32(const void* p) {
    uint32_t a;
    asm("{ .reg .u64 t; cvta.to.shared.u64 t, %1; cvt.u32.u64 %0, t; }"
        : "=r"(a) : "l"(p));
    return a;
}
__device__ __forceinline__ void ldsm_x4(uint32_t* r, uint32_t addr) {
    asm volatile("ldmatrix.sync.aligned.m8n8.x4.shared.b16 {%0,%1,%2,%3}, [%4];"
        : "=r"(r[0]), "=r"(r[1]), "=r"(r[2]), "=r"(r[3]) : "r"(addr));
}
__device__ __forceinline__ void mma16816(float* c, const uint32_t* a, const uint32_t* b) {
    asm volatile(
        "mma.sync.aligned.m16n8k16.row.col.f32.bf16.bf16.f32 "
        "{%0,%1,%2,%3}, {%4,%5,%6,%7}, {%8,%9}, {%0,%1,%2,%3};"
        : "+f"(c[0]), "+f"(c[1]), "+f"(c[2]), "+f"(c[3])
        : "r"(a[0]), "r"(a[1]), "r"(a[2]), "r"(a[3]), "r"(b[0]), "r"(b[1]));
}
__device__ __forceinline__ void split_pair(float a, float b, uint32_t& hi, uint32_t& lo) {
    __nv_bfloat162 h = __floats2bfloat162_rn(a, b);
    float ra = a - __bfloat162float(h.x);
    float rb = b - __bfloat162float(h.y);
    __nv_bfloat162 l = __floats2bfloat162_rn(ra, rb);
    hi = *(uint32_t*)&h;
    lo = *(uint32_t*)&l;
}
__device__ __forceinline__ void cp_async16(uint32_t dst, const void* src) {
    asm volatile("cp.async.cg.shared.global [%0], [%1], 16;" :: "r"(dst), "l"(src));
}
#define CP_COMMIT() asm volatile("cp.async.commit_group;" ::: "memory")
#define CP_WAIT1()  asm volatile("cp.async.wait_group 1;" ::: "memory")
#define CP_WAIT0()  asm volatile("cp.async.wait_group 0;" ::: "memory")

// ===========================================================================
// fp32 -> bf16 hi/lo global split
// ===========================================================================
__global__ void split_f32(const float* __restrict__ src,
                          __nv_bfloat16* __restrict__ hi,
                          __nv_bfloat16* __restrict__ lo, int n8)
{
    int i = blockIdx.x * blockDim.x + threadIdx.x;
    if (i >= n8) return;
    const float4* p = (const float4*)src + 2 * (size_t)i;
    float4 f0 = p[0], f1 = p[1];
    uint4 h, l;
    split_pair(f0.x, f0.y, h.x, l.x);
    split_pair(f0.z, f0.w, h.y, l.y);
    split_pair(f1.x, f1.y, h.z, l.z);
    split_pair(f1.z, f1.w, h.w, l.w);
    ((uint4*)hi)[i] = h;
    ((uint4*)lo)[i] = l;
}

// ===========================================================================
// GEMM mainloop (R9 known-good): 128x128 block, bf16x3, K=2048, 2-stage.
// W pointers are pre-offset to the block's 128 weight rows (bn folded in).
// ===========================================================================
#define GP 40
#define ST_AHI 0
#define ST_ALO (128 * GP)
#define ST_WHI (2 * 128 * GP)
#define ST_WLO (3 * 128 * GP)
#define STAGE_HW (4 * 128 * GP)          // 20480 hw = 40960 B
#define GEMM_SMEM (2 * STAGE_HW * 2)     // 81920 B

__device__ __forceinline__ void gemm_mainloop(
    const uint16_t* __restrict__ Ahi, const uint16_t* __restrict__ Alo,
    const uint16_t* __restrict__ Whi, const uint16_t* __restrict__ Wlo,
    float acc[2][8][4], int bm, uint16_t* smem)
{
    const int K = C_;
    const uint32_t sbase = smem_u32(smem);
    const int tid  = threadIdx.x;
    const int wid  = tid >> 5;
    const int lane = tid & 31;
    const int wm   = wid & 3;
    const int wn   = wid >> 2;

#pragma unroll
    for (int i = 0; i < 2; i++)
#pragma unroll
        for (int j = 0; j < 8; j++)
#pragma unroll
            for (int q = 0; q < 4; q++) acc[i][j][q] = 0.f;

    const int a_row_in = ((lane >> 3) & 1) * 8 + (lane & 7);
    const int a_koff   = (lane >> 4) * 8;
    const int b_row_in = ((lane >> 4) & 1) * 8 + (lane & 7);
    const int b_koff   = ((lane >> 3) & 1) * 8;

#define GEMM_ISSUE(c) do {                                                    \
        int k0_ = (c) * 32;                                                   \
        uint32_t sb_ = sbase + (((c) & 1) * STAGE_HW) * 2;                     \
        _Pragma("unroll")                                                      \
        for (int r_ = 0; r_ < 2; r_++) {                                      \
            int e_  = tid + r_ * 256;                                          \
            int row = e_ >> 2;                                                 \
            int ch  = e_ & 3;                                                  \
            size_t gA = (size_t)(bm + row) * K + k0_ + ch * 8;                 \
            size_t gW = (size_t)row * K + k0_ + ch * 8;                        \
            uint32_t hwo = (row * GP + ch * 8) * 2;                            \
            cp_async16(sb_ + ST_AHI * 2 + hwo, Ahi + gA);                      \
            cp_async16(sb_ + ST_ALO * 2 + hwo, Alo + gA);                      \
            cp_async16(sb_ + ST_WHI * 2 + hwo, Whi + gW);                      \
            cp_async16(sb_ + ST_WLO * 2 + hwo, Wlo + gW);                      \
        }                                                                      \
    } while (0)

    GEMM_ISSUE(0); CP_COMMIT();

    const int nch = K / 32;
    for (int c = 0; c < nch; c++) {
        if (c + 1 < nch) { GEMM_ISSUE(c + 1); CP_COMMIT(); CP_WAIT1(); }
        else             { CP_WAIT0(); }
        __syncthreads();

        const uint32_t sb = sbase + ((c & 1) * STAGE_HW) * 2;
#pragma unroll
        for (int kk = 0; kk < 32; kk += 16) {
            uint32_t aHi[2][4], aLo[2][4], bHi[8][2], bLo[8][2];
#pragma unroll
            for (int mf = 0; mf < 2; mf++) {
                int hw = (wm * 32 + mf * 16 + a_row_in) * GP + kk + a_koff;
                ldsm_x4(aHi[mf], sb + (ST_AHI + hw) * 2);
                ldsm_x4(aLo[mf], sb + (ST_ALO + hw) * 2);
            }
#pragma unroll
            for (int p = 0; p < 4; p++) {
                int hw = (wn * 64 + p * 16 + b_row_in) * GP + kk + b_koff;
                uint32_t rh[4], rl[4];
                ldsm_x4(rh, sb + (ST_WHI + hw) * 2);
                ldsm_x4(rl, sb + (ST_WLO + hw) * 2);
                bHi[2 * p][0] = rh[0]; bHi[2 * p][1] = rh[1];
                bHi[2 * p + 1][0] = rh[2]; bHi[2 * p + 1][1] = rh[3];
                bLo[2 * p][0] = rl[0]; bLo[2 * p][1] = rl[1];
                bLo[2 * p + 1][0] = rl[2]; bLo[2 * p + 1][1] = rl[3];
            }
#pragma unroll
            for (int mf = 0; mf < 2; mf++)
#pragma unroll
                for (int nf = 0; nf < 8; nf++) {
                    mma16816(acc[mf][nf], aHi[mf], bHi[nf]);
                    mma16816(acc[mf][nf], aHi[mf], bLo[nf]);
                    mma16816(acc[mf][nf], aLo[mf], bHi[nf]);
                }
        }
        __syncthreads();
    }
#undef GEMM_ISSUE
}

// ===========================================================================
// Fused q/k/v projection + RoPE + layout scatter + bf16 split (epilogue).
// grid.x regions: [0,16)=q, [16,18)=k, [18,20)=v.
// ===========================================================================
__global__ __launch_bounds__(256)
void gemm_proj(const __nv_bfloat16* __restrict__ xh, const __nv_bfloat16* __restrict__ xl,
               const __nv_bfloat16* __restrict__ wqh, const __nv_bfloat16* __restrict__ wql,
               const __nv_bfloat16* __restrict__ wkh, const __nv_bfloat16* __restrict__ wkl,
               const __nv_bfloat16* __restrict__ wvh, const __nv_bfloat16* __restrict__ wvl,
               const float* __restrict__ cosT, const float* __restrict__ sinT,
               float* __restrict__ out_k, float* __restrict__ out_v,
               __nv_bfloat16* __restrict__ qh, __nv_bfloat16* __restrict__ ql,
               __nv_bfloat16* __restrict__ kh, __nv_bfloat16* __restrict__ kl,
               __nv_bfloat16* __restrict__ vh, __nv_bfloat16* __restrict__ vl)
{
    extern __shared__ __align__(16) uint16_t smem[];
    const int bx = blockIdx.x;
    const int bm = blockIdx.y * 128;

    const uint16_t *Whi, *Wlo;
    int mode, hbase;                 // mode: 0=q, 1=k, 2=v
    if (bx < 16) {
        Whi = (const uint16_t*)wqh + (size_t)bx * 128 * C_;
        Wlo = (const uint16_t*)wql + (size_t)bx * 128 * C_;
        mode = 0; hbase = bx * 2;
    } else if (bx < 18) {
        Whi = (const uint16_t*)wkh + (size_t)(bx - 16) * 128 * C_;
        Wlo = (const uint16_t*)wkl + (size_t)(bx - 16) * 128 * C_;
        mode = 1; hbase = (bx - 16) * 2;
    } else {
        Whi = (const uint16_t*)wvh + (size_t)(bx - 18) * 128 * C_;
        Wlo = (const uint16_t*)wvl + (size_t)(bx - 18) * 128 * C_;
        mode = 2; hbase = (bx - 18) * 2;
    }

    float acc[2][8][4];
    gemm_mainloop((const uint16_t*)xh, (const uint16_t*)xl, Whi, Wlo, acc, bm, smem);

    const int tid  = threadIdx.x;
    const int wid  = tid >> 5;
    const int lane = tid & 31;
    const int wm   = wid & 3;
    const int wn   = wid >> 2;
    const int gq   = lane >> 2;
    const int qt   = lane & 3;
    const int h    = hbase + wn;

#pragma unroll
    for (int mf = 0; mf < 2; mf++) {
        int row0 = bm + wm * 32 + mf * 16 + gq;
        int row1 = row0 + 8;
        int t0 = row0 & (T_ - 1), b0 = row0 >> 11;
        int t1 = row1 & (T_ - 1), b1 = row1 >> 11;
#pragma unroll
        for (int nf = 0; nf < 8; nf++) {
            int d = nf * 8 + qt * 2;                 // even, 0..62
            float v00 = acc[mf][nf][0], v01 = acc[mf][nf][1];
            float v10 = acc[mf][nf][2], v11 = acc[mf][nf][3];
            float o00, o01, o10, o11;
            if (mode == 2) {
                o00 = v00; o01 = v01; o10 = v10; o11 = v11;
            } else {
                float2 c0 = *(const float2*)(cosT + t0 * D_ + d);
                float2 s0 = *(const float2*)(sinT + t0 * D_ + d);
                float2 c1 = *(const float2*)(cosT + t1 * D_ + d);
                float2 s1 = *(const float2*)(sinT + t1 * D_ + d);
                o00 = v00 * c0.x - v01 * s0.x;
                o01 = v01 * c0.y + v00 * s0.y;
                o10 = v10 * c1.x - v11 * s1.x;
                o11 = v11 * c1.y + v10 * s1.y;
                if (mode == 0) { o00 *= 0.125f; o01 *= 0.125f;
                                 o10 *= 0.125f; o11 *= 0.125f; }
            }
            uint32_t hw, lw;
            if (mode == 0) {
                size_t i0 = (((size_t)b0 * H_ + h) * T_ + t0) * D_ + d;
                size_t i1 = (((size_t)b1 * H_ + h) * T_ + t1) * D_ + d;
                split_pair(o00, o01, hw, lw);
                *(uint32_t*)((uint16_t*)qh + i0) = hw;
                *(uint32_t*)((uint16_t*)ql + i0) = lw;
                split_pair(o10, o11, hw, lw);
                *(uint32_t*)((uint16_t*)qh + i1) = hw;
                *(uint32_t*)((uint16_t*)ql + i1) = lw;
            } else {
                size_t i0 = (((size_t)b0 * HK_ + h) * T_ + t0) * D_ + d;
                size_t i1 = (((size_t)b1 * HK_ + h) * T_ + t1) * D_ + d;
                float* outF = (mode == 1) ? out_k : out_v;
                uint16_t* dH = (mode == 1) ? (uint16_t*)kh : (uint16_t*)vh;
                uint16_t* dL = (mode == 1) ? (uint16_t*)kl : (uint16_t*)vl;
                *(float2*)(outF + i0) = make_float2(o00, o01);
                *(float2*)(outF + i1) = make_float2(o10, o11);
                split_pair(o00, o01, hw, lw);
                *(uint32_t*)(dH + i0) = hw;
                *(uint32_t*)(dL + i0) = lw;
                split_pair(o10, o11, hw, lw);
                *(uint32_t*)(dH + i1) = hw;
                *(uint32_t*)(dL + i1) = lw;
            }
        }
    }
}

// Output projection: standard fp32 store
__global__ __launch_bounds__(256)
void gemm_out(const __nv_bfloat16* __restrict__ oh, const __nv_bfloat16* __restrict__ ol,
              const __nv_bfloat16* __restrict__ woh, const __nv_bfloat16* __restrict__ wol,
              float* __restrict__ out)
{
    extern __shared__ __align__(16) uint16_t smem[];
    const int bm = blockIdx.y * 128;
    const int bn = blockIdx.x * 128;
    float acc[2][8][4];
    gemm_mainloop((const uint16_t*)oh, (const uint16_t*)ol,
                  (const uint16_t*)woh + (size_t)bn * C_,
                  (const uint16_t*)wol + (size_t)bn * C_,
                  acc, bm, smem);

    const int tid  = threadIdx.x;
    const int wid  = tid >> 5;
    const int lane = tid & 31;
    const int wm   = wid & 3;
    const int wn   = wid >> 2;
    const int gq   = lane >> 2;
    const int qt   = lane & 3;
#pragma unroll
    for (int mf = 0; mf < 2; mf++) {
#pragma unroll
        for (int nf = 0; nf < 8; nf++) {
            int row0 = bm + wm * 32 + mf * 16 + gq;
            int col  = bn + wn * 64 + nf * 8 + qt * 2;
            *(float2*)(out + (size_t)row0 * C_ + col) =
                make_float2(acc[mf][nf][0], acc[mf][nf][1]);
            *(float2*)(out + (size_t)(row0 + 8) * C_ + col) =
                make_float2(acc[mf][nf][2], acc[mf][nf][3]);
        }
    }
}

// ===========================================================================
// Tensor-core causal flash attention (R9 known-good): Br=64, 128 threads.
// ===========================================================================
#define FP 72
#define FK_HI 0
#define FK_LO 4608
#define FV_HI 9216
#define FV_LO 13824

__global__ __launch_bounds__(128)
void flash_mma(const __nv_bfloat16* __restrict__ Qh, const __nv_bfloat16* __restrict__ Ql,
               const __nv_bfloat16* __restrict__ Kh, const __nv_bfloat16* __restrict__ Kl,
               const __nv_bfloat16* __restrict__ Vh, const __nv_bfloat16* __restrict__ Vl,
               __nv_bfloat16* __restrict__ Oh, __nv_bfloat16* __restrict__ Ol)
{
    __shared__ __align__(16) uint16_t buf[18432];

    const int qb  = blockIdx.x;
    const int bh  = blockIdx.y;
    const int b   = bh >> 5;
    const int h   = bh & 31;
    const int kh  = h >> 3;
    const int tid = threadIdx.x;
    const int wm  = tid >> 5;
    const int lane = tid & 31;
    const int gq  = lane >> 2;
    const int qt  = lane & 3;
    const int q0  = qb * 64;

    const uint16_t* Qhp = (const uint16_t*)Qh + ((size_t)bh * T_ + q0) * D_;
    const uint16_t* Qlp = (const uint16_t*)Ql + ((size_t)bh * T_ + q0) * D_;
    const size_t kvoff = ((size_t)(b * HK_ + kh) * T_) * D_;
    const uint16_t* Khp = (const uint16_t*)Kh + kvoff;
    const uint16_t* Klp = (const uint16_t*)Kl + kvoff;
    const uint16_t* Vhp = (const uint16_t*)Vh + kvoff;
    const uint16_t* Vlp = (const uint16_t*)Vl + kvoff;

    const uint32_t sbase = smem_u32(buf);

    {
        int row = tid >> 1;
        int kc  = tid & 1;
#pragma unroll
        for (int g = 0; g < 4; g++) {
            int ch  = kc * 4 + g;
            size_t src = (size_t)row * D_ + ch * 8;
            uint32_t dsthw = row * FP + ch * 8;
            cp_async16(sbase + (FK_HI + dsthw) * 2, Qhp + src);
            cp_async16(sbase + (FK_LO + dsthw) * 2, Qlp + src);
        }
    }
    CP_COMMIT(); CP_WAIT0();
    __syncthreads();

    const int a_row = ((lane >> 3) & 1) * 8 + (lane & 7);
    const int a_k   = (lane >> 4) * 8;
    const int b_row = ((lane >> 4) & 1) * 8 + (lane & 7);
    const int b_k   = ((lane >> 3) & 1) * 8;

    uint32_t qhi[4][4], qlo[4][4];
#pragma unroll
    for (int dk = 0; dk < 4; dk++) {
        int hw = (wm * 16 + a_row) * FP + dk * 16 + a_k;
        ldsm_x4(qhi[dk], sbase + 2 * (FK_HI + hw));
        ldsm_x4(qlo[dk], sbase + 2 * (FK_LO + hw));
    }
    __syncthreads();

    float m0 = -1e30f, m1 = -1e30f, l0 = 0.f, l1 = 0.f;
    float o[8][4];
#pragma unroll
    for (int nf = 0; nf < 8; nf++)
#pragma unroll
        for (int q = 0; q < 4; q++) o[nf][q] = 0.f;

    for (int kb = 0; kb <= qb; kb++) {
        {
            int row = tid >> 1;
            int kc  = tid & 1;
#pragma unroll
            for (int g = 0; g < 4; g++) {
                int ch  = kc * 4 + g;
                size_t src = (size_t)(kb * 64 + row) * D_ + ch * 8;
                uint32_t dsthw = row * FP + ch * 8;
                cp_async16(sbase + (FK_HI + dsthw) * 2, Khp + src);
                cp_async16(sbase + (FK_LO + dsthw) * 2, Klp + src);
            }
        }
        CP_COMMIT();

#pragma unroll
        for (int u2 = 0; u2 < 2; u2++) {
            int u  = tid + u2 * 128;
            int s0 = 2 * (u & 31);
            int d0 = 8 * (u >> 5);
            size_t g0 = (size_t)(kb * 64 + s0) * D_ + d0;
            uint4 h0 = *(const uint4*)(Vhp + g0);
            uint4 h1 = *(const uint4*)(Vhp + g0 + D_);
            uint4 l0v = *(const uint4*)(Vlp + g0);
            uint4 l1v = *(const uint4*)(Vlp + g0 + D_);
            const uint32_t* a0 = (const uint32_t*)&h0;
            const uint32_t* a1 = (const uint32_t*)&h1;
            const uint32_t* c0 = (const uint32_t*)&l0v;
            const uint32_t* c1 = (const uint32_t*)&l1v;
#pragma unroll
            for (int j = 0; j < 4; j++) {
                uint32_t ah = a0[j], bhw = a1[j];
                uint32_t al = c0[j], blw = c1[j];
                int d = d0 + 2 * j;
                *(uint32_t*)&buf[FV_HI + d * FP + s0] = (ah & 0xffffu) | (bhw << 16);
                *(uint32_t*)&buf[FV_HI + (d + 1) * FP + s0] = (ah >> 16) | (bhw & 0xffff0000u);
                *(uint32_t*)&buf[FV_LO + d * FP + s0] = (al & 0xffffu) | (blw << 16);
                *(uint32_t*)&buf[FV_LO + (d + 1) * FP + s0] = (al >> 16) | (blw & 0xffff0000u);
            }
        }
        CP_WAIT0();
        __syncthreads();

        float s[8][4];
#pragma unroll
        for (int nf = 0; nf < 8; nf++)
#pragma unroll
            for (int q = 0; q < 4; q++) s[nf][q] = 0.f;

#pragma unroll
        for (int dk = 0; dk < 4; dk++) {
            uint32_t kfh[4][4], kfl[4][4];
#pragma unroll
            for (int g = 0; g < 4; g++) {
                int hw = (16 * g + b_row) * FP + dk * 16 + b_k;
                ldsm_x4(kfh[g], sbase + 2 * (FK_HI + hw));
                ldsm_x4(kfl[g], sbase + 2 * (FK_LO + hw));
            }
#pragma unroll
            for (int g = 0; g < 4; g++) {
                mma16816(s[2 * g],     qhi[dk], &kfh[g][0]);
                mma16816(s[2 * g],     qhi[dk], &kfl[g][0]);
                mma16816(s[2 * g],     qlo[dk], &kfh[g][0]);
                mma16816(s[2 * g + 1], qhi[dk], &kfh[g][2]);
                mma16816(s[2 * g + 1], qhi[dk], &kfl[g][2]);
                mma16816(s[2 * g + 1], qlo[dk], &kfh[g][2]);
            }
        }

        if (kb == qb) {
            int r0g = 16 * wm + gq;
            int r1g = r0g + 8;
#pragma unroll
            for (int nf = 0; nf < 8; nf++) {
                int c = nf * 8 + 2 * qt;
                if (c     > r0g) s[nf][0] = -1e30f;
                if (c + 1 > r0g) s[nf][1] = -1e30f;
                if (c     > r1g) s[nf][2] = -1e30f;
                if (c + 1 > r1g) s[nf][3] = -1e30f;
            }
        }

        float mx0 = -1e30f, mx1 = -1e30f;
#pragma unroll
        for (int nf = 0; nf < 8; nf++) {
            mx0 = fmaxf(mx0, fmaxf(s[nf][0], s[nf][1]));
            mx1 = fmaxf(mx1, fmaxf(s[nf][2], s[nf][3]));
        }
        mx0 = fmaxf(mx0, __shfl_xor_sync(0xffffffffu, mx0, 1));
        mx0 = fmaxf(mx0, __shfl_xor_sync(0xffffffffu, mx0, 2));
        mx1 = fmaxf(mx1, __shfl_xor_sync(0xffffffffu, mx1, 1));
        mx1 = fmaxf(mx1, __shfl_xor_sync(0xffffffffu, mx1, 2));
        float mn0 = fmaxf(m0, mx0), mn1 = fmaxf(m1, mx1);
        float al0 = __expf(m0 - mn0), al1 = __expf(m1 - mn1);
        float sum0 = 0.f, sum1 = 0.f;
#pragma unroll
        for (int nf = 0; nf < 8; nf++) {
            s[nf][0] = __expf(s[nf][0] - mn0);
            s[nf][1] = __expf(s[nf][1] - mn0);
            s[nf][2] = __expf(s[nf][2] - mn1);
            s[nf][3] = __expf(s[nf][3] - mn1);
            sum0 += s[nf][0] + s[nf][1];
            sum1 += s[nf][2] + s[nf][3];
        }
        sum0 += __shfl_xor_sync(0xffffffffu, sum0, 1);
        sum0 += __shfl_xor_sync(0xffffffffu, sum0, 2);
        sum1 += __shfl_xor_sync(0xffffffffu, sum1, 1);
        sum1 += __shfl_xor_sync(0xffffffffu, sum1, 2);
        l0 = l0 * al0 + sum0;  m0 = mn0;
        l1 = l1 * al1 + sum1;  m1 = mn1;
#pragma unroll
        for (int nf = 0; nf < 8; nf++) {
            o[nf][0] *= al0; o[nf][1] *= al0;
            o[nf][2] *= al1; o[nf][3] *= al1;
        }

        uint32_t phi[4][4], plo[4][4];
#pragma unroll
        for (int kc = 0; kc < 4; kc++) {
            split_pair(s[2 * kc][0],     s[2 * kc][1],     phi[kc][0], plo[kc][0]);
            split_pair(s[2 * kc][2],     s[2 * kc][3],     phi[kc][1], plo[kc][1]);
            split_pair(s[2 * kc + 1][0], s[2 * kc + 1][1], phi[kc][2], plo[kc][2]);
            split_pair(s[2 * kc + 1][2], s[2 * kc + 1][3], phi[kc][3], plo[kc][3]);
        }

#pragma unroll
        for (int kc = 0; kc < 4; kc++) {
            uint32_t vfh[4][4], vfl[4][4];
#pragma unroll
            for (int g = 0; g < 4; g++) {
                int hw = (16 * g + b_row) * FP + kc * 16 + b_k;
                ldsm_x4(vfh[g], sbase + 2 * (FV_HI + hw));
                ldsm_x4(vfl[g], sbase + 2 * (FV_LO + hw));
            }
#pragma unroll
            for (int g = 0; g < 4; g++) {
                mma16816(o[2 * g],     phi[kc], &vfh[g][0]);
                mma16816(o[2 * g],     phi[kc], &vfl[g][0]);
                mma16816(o[2 * g],     plo[kc], &vfh[g][0]);
                mma16816(o[2 * g + 1], phi[kc], &vfh[g][2]);
                mma16816(o[2 * g + 1], phi[kc], &vfl[g][2]);
                mma16816(o[2 * g + 1], plo[kc], &vfh[g][2]);
            }
        }
        __syncthreads();
    }

    float inv0 = 1.0f / l0, inv1 = 1.0f / l1;
    int row0 = q0 + wm * 16 + gq;
    size_t base0 = ((size_t)b * T_ + row0) * (H_ * D_) + h * D_;
    size_t base1 = base0 + (size_t)8 * (H_ * D_);
    uint16_t* OhP = (uint16_t*)Oh;
    uint16_t* OlP = (uint16_t*)Ol;
#pragma unroll
    for (int nf = 0; nf < 8; nf++) {
        int c = nf * 8 + 2 * qt;
        uint32_t hw, lw;
        split_pair(o[nf][0] * inv0, o[nf][1] * inv0, hw, lw);
        *(uint32_t*)(OhP + base0 + c) = hw;
        *(uint32_t*)(OlP + base0 + c) = lw;
        split_pair(o[nf][2] * inv1, o[nf][3] * inv1, hw, lw);
        *(uint32_t*)(OhP + base1 + c) = hw;
        *(uint32_t*)(OlP + base1 + c) = lw;
    }
}

// ===========================================================================
extern "C" void kernel_launch(void* const* d_in, const int* in_sizes, int n_in,
                              void* d_out, int out_size)
{
    const float* x    = (const float*)d_in[0];
    const float* cosT = (const float*)d_in[1];
    const float* sinT = (const float*)d_in[2];
    const float* wq   = (const float*)d_in[3];
    const float* wk   = (const float*)d_in[4];
    const float* wv   = (const float*)d_in[5];
    const float* wo   = (const float*)d_in[6];

    float* out   = (float*)d_out;
    float* out_k = out   + (size_t)B_ * T_ * C_;
    float* out_v = out_k + (size_t)B_ * HK_ * T_ * D_;

    __nv_bfloat16 *xh, *xl, *oh, *ol, *wqh, *wql, *wkh, *wkl, *wvh, *wvl, *woh, *wol;
    __nv_bfloat16 *qh, *ql, *kh, *kl, *vh, *vl;
    cudaGetSymbolAddress((void**)&xh, g_xh);   cudaGetSymbolAddress((void**)&xl, g_xl);
    cudaGetSymbolAddress((void**)&oh, g_oh);   cudaGetSymbolAddress((void**)&ol, g_ol);
    cudaGetSymbolAddress((void**)&wqh, g_wqh); cudaGetSymbolAddress((void**)&wql, g_wql);
    cudaGetSymbolAddress((void**)&wkh, g_wkh); cudaGetSymbolAddress((void**)&wkl, g_wkl);
    cudaGetSymbolAddress((void**)&wvh, g_wvh); cudaGetSymbolAddress((void**)&wvl, g_wvl);
    cudaGetSymbolAddress((void**)&woh, g_woh); cudaGetSymbolAddress((void**)&wol, g_wol);
    cudaGetSymbolAddress((void**)&qh, g_qh);   cudaGetSymbolAddress((void**)&ql, g_ql);
    cudaGetSymbolAddress((void**)&kh, g_kh);   cudaGetSymbolAddress((void**)&kl, g_kl);
    cudaGetSymbolAddress((void**)&vh, g_vh);   cudaGetSymbolAddress((void**)&vl, g_vl);

    cudaFuncSetAttribute(gemm_proj,
                         cudaFuncAttributeMaxDynamicSharedMemorySize, GEMM_SMEM);
    cudaFuncSetAttribute(gemm_out,
                         cudaFuncAttributeMaxDynamicSharedMemorySize, GEMM_SMEM);

    // ---- pre-split inputs into bf16 hi/lo ----
    {
        int nx = (MROWS * C_) / 8;
        int nw = ((H_ * D_) * C_) / 8;
        int ns = ((HK_ * D_) * C_) / 8;
        split_f32<<<(nx + 255) / 256, 256>>>(x,  xh,  xl,  nx);
        split_f32<<<(nw + 255) / 256, 256>>>(wq, wqh, wql, nw);
        split_f32<<<(ns + 255) / 256, 256>>>(wk, wkh, wkl, ns);
        split_f32<<<(ns + 255) / 256, 256>>>(wv, wvh, wvl, ns);
        split_f32<<<(nw + 255) / 256, 256>>>(wo, woh, wol, nw);
    }

    // ---- fused q/k/v projections + RoPE + scatter + split ----
    gemm_proj<<<dim3(20, MROWS / 128), 256, GEMM_SMEM>>>(
        xh, xl, wqh, wql, wkh, wkl, wvh, wvl,
        cosT, sinT, out_k, out_v, qh, ql, kh, kl, vh, vl);

    // ---- flash attention ----
    flash_mma<<<dim3(T_ / 64, B_ * H_), 128>>>(qh, ql, kh, kl, vh, vl, oh, ol);

    // ---- output projection ----
    gemm_out<<<dim3(C_ / 128, MROWS / 128), 256, GEMM_SMEM>>>(oh, ol, woh, wol, out);
}

// round 13
// speedup vs baseline: 1.0931x; 1.0169x over previous
#include <cuda_runtime.h>
#include <cuda_bf16.h>
#include <math.h>
#include <stdint.h>

// Problem constants
#define B_   2
#define T_   2048
#define C_   2048
#define H_   32
#define HK_  4
#define D_   64
#define MROWS (B_ * T_)          // 4096

// ---------------- scratch (static device globals; no allocation) ----------
__device__ __nv_bfloat16 g_xh[(long long)MROWS * C_],  g_xl[(long long)MROWS * C_];
__device__ __nv_bfloat16 g_oh[(long long)MROWS * C_],  g_ol[(long long)MROWS * C_];
__device__ __nv_bfloat16 g_wqh[(long long)(H_*D_) * C_],  g_wql[(long long)(H_*D_) * C_];
__device__ __nv_bfloat16 g_wkh[(long long)(HK_*D_) * C_], g_wkl[(long long)(HK_*D_) * C_];
__device__ __nv_bfloat16 g_wvh[(long long)(HK_*D_) * C_], g_wvl[(long long)(HK_*D_) * C_];
__device__ __nv_bfloat16 g_woh[(long long)C_ * (H_*D_)],  g_wol[(long long)C_ * (H_*D_)];
__device__ __nv_bfloat16 g_qh[(long long)B_*H_*T_*D_],  g_ql[(long long)B_*H_*T_*D_];
__device__ __nv_bfloat16 g_kh[(long long)B_*HK_*T_*D_], g_kl[(long long)B_*HK_*T_*D_];
__device__ __nv_bfloat16 g_vh[(long long)B_*HK_*T_*D_], g_vl[(long long)B_*HK_*T_*D_];

// ===========================================================================
// helpers
// ===========================================================================
__device__ __forceinline__ uint32_t smem_u32(const void* p) {
    uint32_t a;
    asm("{ .reg .u64 t; cvta.to.shared.u64 t, %1; cvt.u32.u64 %0, t; }"
        : "=r"(a) : "l"(p));
    return a;
}
__device__ __forceinline__ void ldsm_x4(uint32_t* r, uint32_t addr) {
    asm volatile("ldmatrix.sync.aligned.m8n8.x4.shared.b16 {%0,%1,%2,%3}, [%4];"
        : "=r"(r[0]), "=r"(r[1]), "=r"(r[2]), "=r"(r[3]) : "r"(addr));
}
__device__ __forceinline__ void mma16816(float* c, const uint32_t* a, const uint32_t* b) {
    asm volatile(
        "mma.sync.aligned.m16n8k16.row.col.f32.bf16.bf16.f32 "
        "{%0,%1,%2,%3}, {%4,%5,%6,%7}, {%8,%9}, {%0,%1,%2,%3};"
        : "+f"(c[0]), "+f"(c[1]), "+f"(c[2]), "+f"(c[3])
        : "r"(a[0]), "r"(a[1]), "r"(a[2]), "r"(a[3]), "r"(b[0]), "r"(b[1]));
}
__device__ __forceinline__ void split_pair(float a, float b, uint32_t& hi, uint32_t& lo) {
    __nv_bfloat162 h = __floats2bfloat162_rn(a, b);
    float ra = a - __bfloat162float(h.x);
    float rb = b - __bfloat162float(h.y);
    __nv_bfloat162 l = __floats2bfloat162_rn(ra, rb);
    hi = *(uint32_t*)&h;
    lo = *(uint32_t*)&l;
}
__device__ __forceinline__ void cp_async16(uint32_t dst, const void* src) {
    asm volatile("cp.async.cg.shared.global [%0], [%1], 16;" :: "r"(dst), "l"(src));
}
#define CP_COMMIT() asm volatile("cp.async.commit_group;" ::: "memory")
#define CP_WAIT1()  asm volatile("cp.async.wait_group 1;" ::: "memory")
#define CP_WAIT0()  asm volatile("cp.async.wait_group 0;" ::: "memory")

// ===========================================================================
// fp32 -> bf16 hi/lo global split
// ===========================================================================
__global__ void split_f32(const float* __restrict__ src,
                          __nv_bfloat16* __restrict__ hi,
                          __nv_bfloat16* __restrict__ lo, int n8)
{
    int i = blockIdx.x * blockDim.x + threadIdx.x;
    if (i >= n8) return;
    const float4* p = (const float4*)src + 2 * (size_t)i;
    float4 f0 = p[0], f1 = p[1];
    uint4 h, l;
    split_pair(f0.x, f0.y, h.x, l.x);
    split_pair(f0.z, f0.w, h.y, l.y);
    split_pair(f1.x, f1.y, h.z, l.z);
    split_pair(f1.z, f1.w, h.w, l.w);
    ((uint4*)hi)[i] = h;
    ((uint4*)lo)[i] = l;
}

// ===========================================================================
// GEMM mainloop: 128x128 block, bf16x3, K=2048, 2-stage cp.async.
// Register-lean variant: B fragments streamed per p-group (no [8][2] buffer)
// so the kernel fits 128 regs/thread => 2 CTAs/SM hide the chunk barrier.
// W pointers are pre-offset to the block's 128 weight rows.
// ===========================================================================
#define GP 40
#define ST_AHI 0
#define ST_ALO (128 * GP)
#define ST_WHI (2 * 128 * GP)
#define ST_WLO (3 * 128 * GP)
#define STAGE_HW (4 * 128 * GP)          // 20480 hw = 40960 B
#define GEMM_SMEM (2 * STAGE_HW * 2)     // 81920 B

__device__ __forceinline__ void gemm_mainloop(
    const uint16_t* __restrict__ Ahi, const uint16_t* __restrict__ Alo,
    const uint16_t* __restrict__ Whi, const uint16_t* __restrict__ Wlo,
    float acc[2][8][4], int bm, uint16_t* smem)
{
    const int K = C_;
    const uint32_t sbase = smem_u32(smem);
    const int tid  = threadIdx.x;
    const int wid  = tid >> 5;
    const int lane = tid & 31;
    const int wm   = wid & 3;
    const int wn   = wid >> 2;

#pragma unroll
    for (int i = 0; i < 2; i++)
#pragma unroll
        for (int j = 0; j < 8; j++)
#pragma unroll
            for (int q = 0; q < 4; q++) acc[i][j][q] = 0.f;

    const int a_row_in = ((lane >> 3) & 1) * 8 + (lane & 7);
    const int a_koff   = (lane >> 4) * 8;
    const int b_row_in = ((lane >> 4) & 1) * 8 + (lane & 7);
    const int b_koff   = ((lane >> 3) & 1) * 8;

#define GEMM_ISSUE(c) do {                                                    \
        int k0_ = (c) * 32;                                                   \
        uint32_t sb_ = sbase + (((c) & 1) * STAGE_HW) * 2;                     \
        _Pragma("unroll")                                                      \
        for (int r_ = 0; r_ < 2; r_++) {                                      \
            int e_  = tid + r_ * 256;                                          \
            int row = e_ >> 2;                                                 \
            int ch  = e_ & 3;                                                  \
            size_t gA = (size_t)(bm + row) * K + k0_ + ch * 8;                 \
            size_t gW = (size_t)row * K + k0_ + ch * 8;                        \
            uint32_t hwo = (row * GP + ch * 8) * 2;                            \
            cp_async16(sb_ + ST_AHI * 2 + hwo, Ahi + gA);                      \
            cp_async16(sb_ + ST_ALO * 2 + hwo, Alo + gA);                      \
            cp_async16(sb_ + ST_WHI * 2 + hwo, Whi + gW);                      \
            cp_async16(sb_ + ST_WLO * 2 + hwo, Wlo + gW);                      \
        }                                                                      \
    } while (0)

    GEMM_ISSUE(0); CP_COMMIT();

    const int nch = K / 32;
    for (int c = 0; c < nch; c++) {
        if (c + 1 < nch) { GEMM_ISSUE(c + 1); CP_COMMIT(); CP_WAIT1(); }
        else             { CP_WAIT0(); }
        __syncthreads();

        const uint32_t sb = sbase + ((c & 1) * STAGE_HW) * 2;
#pragma unroll
        for (int kk = 0; kk < 32; kk += 16) {
            uint32_t aHi[2][4], aLo[2][4];
#pragma unroll
            for (int mf = 0; mf < 2; mf++) {
                int hw = (wm * 32 + mf * 16 + a_row_in) * GP + kk + a_koff;
                ldsm_x4(aHi[mf], sb + (ST_AHI + hw) * 2);
                ldsm_x4(aLo[mf], sb + (ST_ALO + hw) * 2);
            }
            // stream B fragments per p-group (keeps live regs < 128)
#pragma unroll
            for (int p = 0; p < 4; p++) {
                int hw = (wn * 64 + p * 16 + b_row_in) * GP + kk + b_koff;
                uint32_t rh[4], rl[4];
                ldsm_x4(rh, sb + (ST_WHI + hw) * 2);
                ldsm_x4(rl, sb + (ST_WLO + hw) * 2);
#pragma unroll
                for (int mf = 0; mf < 2; mf++) {
                    mma16816(acc[mf][2 * p],     aHi[mf], &rh[0]);
                    mma16816(acc[mf][2 * p],     aHi[mf], &rl[0]);
                    mma16816(acc[mf][2 * p],     aLo[mf], &rh[0]);
                    mma16816(acc[mf][2 * p + 1], aHi[mf], &rh[2]);
                    mma16816(acc[mf][2 * p + 1], aHi[mf], &rl[2]);
                    mma16816(acc[mf][2 * p + 1], aLo[mf], &rh[2]);
                }
            }
        }
        __syncthreads();
    }
#undef GEMM_ISSUE
}

// ===========================================================================
// Fused q/k/v projection + RoPE + layout scatter + bf16 split (epilogue).
// grid.x regions: [0,16)=q, [16,18)=k, [18,20)=v.
// ===========================================================================
__global__ __launch_bounds__(256, 2)
void gemm_proj(const __nv_bfloat16* __restrict__ xh, const __nv_bfloat16* __restrict__ xl,
               const __nv_bfloat16* __restrict__ wqh, const __nv_bfloat16* __restrict__ wql,
               const __nv_bfloat16* __restrict__ wkh, const __nv_bfloat16* __restrict__ wkl,
               const __nv_bfloat16* __restrict__ wvh, const __nv_bfloat16* __restrict__ wvl,
               const float* __restrict__ cosT, const float* __restrict__ sinT,
               float* __restrict__ out_k, float* __restrict__ out_v,
               __nv_bfloat16* __restrict__ qh, __nv_bfloat16* __restrict__ ql,
               __nv_bfloat16* __restrict__ kh, __nv_bfloat16* __restrict__ kl,
               __nv_bfloat16* __restrict__ vh, __nv_bfloat16* __restrict__ vl)
{
    extern __shared__ __align__(16) uint16_t smem[];
    const int bx = blockIdx.x;
    const int bm = blockIdx.y * 128;

    const uint16_t *Whi, *Wlo;
    int mode, hbase;                 // mode: 0=q, 1=k, 2=v
    if (bx < 16) {
        Whi = (const uint16_t*)wqh + (size_t)bx * 128 * C_;
        Wlo = (const uint16_t*)wql + (size_t)bx * 128 * C_;
        mode = 0; hbase = bx * 2;
    } else if (bx < 18) {
        Whi = (const uint16_t*)wkh + (size_t)(bx - 16) * 128 * C_;
        Wlo = (const uint16_t*)wkl + (size_t)(bx - 16) * 128 * C_;
        mode = 1; hbase = (bx - 16) * 2;
    } else {
        Whi = (const uint16_t*)wvh + (size_t)(bx - 18) * 128 * C_;
        Wlo = (const uint16_t*)wvl + (size_t)(bx - 18) * 128 * C_;
        mode = 2; hbase = (bx - 18) * 2;
    }

    float acc[2][8][4];
    gemm_mainloop((const uint16_t*)xh, (const uint16_t*)xl, Whi, Wlo, acc, bm, smem);

    const int tid  = threadIdx.x;
    const int wid  = tid >> 5;
    const int lane = tid & 31;
    const int wm   = wid & 3;
    const int wn   = wid >> 2;
    const int gq   = lane >> 2;
    const int qt   = lane & 3;
    const int h    = hbase + wn;

#pragma unroll
    for (int mf = 0; mf < 2; mf++) {
        int row0 = bm + wm * 32 + mf * 16 + gq;
        int row1 = row0 + 8;
        int t0 = row0 & (T_ - 1), b0 = row0 >> 11;
        int t1 = row1 & (T_ - 1), b1 = row1 >> 11;
#pragma unroll
        for (int nf = 0; nf < 8; nf++) {
            int d = nf * 8 + qt * 2;                 // even, 0..62
            float v00 = acc[mf][nf][0], v01 = acc[mf][nf][1];
            float v10 = acc[mf][nf][2], v11 = acc[mf][nf][3];
            float o00, o01, o10, o11;
            if (mode == 2) {
                o00 = v00; o01 = v01; o10 = v10; o11 = v11;
            } else {
                float2 c0 = *(const float2*)(cosT + t0 * D_ + d);
                float2 s0 = *(const float2*)(sinT + t0 * D_ + d);
                float2 c1 = *(const float2*)(cosT + t1 * D_ + d);
                float2 s1 = *(const float2*)(sinT + t1 * D_ + d);
                o00 = v00 * c0.x - v01 * s0.x;
                o01 = v01 * c0.y + v00 * s0.y;
                o10 = v10 * c1.x - v11 * s1.x;
                o11 = v11 * c1.y + v10 * s1.y;
                if (mode == 0) { o00 *= 0.125f; o01 *= 0.125f;
                                 o10 *= 0.125f; o11 *= 0.125f; }
            }
            uint32_t hw, lw;
            if (mode == 0) {
                size_t i0 = (((size_t)b0 * H_ + h) * T_ + t0) * D_ + d;
                size_t i1 = (((size_t)b1 * H_ + h) * T_ + t1) * D_ + d;
                split_pair(o00, o01, hw, lw);
                *(uint32_t*)((uint16_t*)qh + i0) = hw;
                *(uint32_t*)((uint16_t*)ql + i0) = lw;
                split_pair(o10, o11, hw, lw);
                *(uint32_t*)((uint16_t*)qh + i1) = hw;
                *(uint32_t*)((uint16_t*)ql + i1) = lw;
            } else {
                size_t i0 = (((size_t)b0 * HK_ + h) * T_ + t0) * D_ + d;
                size_t i1 = (((size_t)b1 * HK_ + h) * T_ + t1) * D_ + d;
                float* outF = (mode == 1) ? out_k : out_v;
                uint16_t* dH = (mode == 1) ? (uint16_t*)kh : (uint16_t*)vh;
                uint16_t* dL = (mode == 1) ? (uint16_t*)kl : (uint16_t*)vl;
                *(float2*)(outF + i0) = make_float2(o00, o01);
                *(float2*)(outF + i1) = make_float2(o10, o11);
                split_pair(o00, o01, hw, lw);
                *(uint32_t*)(dH + i0) = hw;
                *(uint32_t*)(dL + i0) = lw;
                split_pair(o10, o11, hw, lw);
                *(uint32_t*)(dH + i1) = hw;
                *(uint32_t*)(dL + i1) = lw;
            }
        }
    }
}

// Output projection: standard fp32 store
__global__ __launch_bounds__(256, 2)
void gemm_out(const __nv_bfloat16* __restrict__ oh, const __nv_bfloat16* __restrict__ ol,
              const __nv_bfloat16* __restrict__ woh, const __nv_bfloat16* __restrict__ wol,
              float* __restrict__ out)
{
    extern __shared__ __align__(16) uint16_t smem[];
    const int bm = blockIdx.y * 128;
    const int bn = blockIdx.x * 128;
    float acc[2][8][4];
    gemm_mainloop((const uint16_t*)oh, (const uint16_t*)ol,
                  (const uint16_t*)woh + (size_t)bn * C_,
                  (const uint16_t*)wol + (size_t)bn * C_,
                  acc, bm, smem);

    const int tid  = threadIdx.x;
    const int wid  = tid >> 5;
    const int lane = tid & 31;
    const int wm   = wid & 3;
    const int wn   = wid >> 2;
    const int gq   = lane >> 2;
    const int qt   = lane & 3;
#pragma unroll
    for (int mf = 0; mf < 2; mf++) {
#pragma unroll
        for (int nf = 0; nf < 8; nf++) {
            int row0 = bm + wm * 32 + mf * 16 + gq;
            int col  = bn + wn * 64 + nf * 8 + qt * 2;
            *(float2*)(out + (size_t)row0 * C_ + col) =
                make_float2(acc[mf][nf][0], acc[mf][nf][1]);
            *(float2*)(out + (size_t)(row0 + 8) * C_ + col) =
                make_float2(acc[mf][nf][2], acc[mf][nf][3]);
        }
    }
}

// ===========================================================================
// Tensor-core causal flash attention (R9 known-good): Br=64, 128 threads.
// ===========================================================================
#define FP 72
#define FK_HI 0
#define FK_LO 4608
#define FV_HI 9216
#define FV_LO 13824

__global__ __launch_bounds__(128)
void flash_mma(const __nv_bfloat16* __restrict__ Qh, const __nv_bfloat16* __restrict__ Ql,
               const __nv_bfloat16* __restrict__ Kh, const __nv_bfloat16* __restrict__ Kl,
               const __nv_bfloat16* __restrict__ Vh, const __nv_bfloat16* __restrict__ Vl,
               __nv_bfloat16* __restrict__ Oh, __nv_bfloat16* __restrict__ Ol)
{
    __shared__ __align__(16) uint16_t buf[18432];

    const int qb  = blockIdx.x;
    const int bh  = blockIdx.y;
    const int b   = bh >> 5;
    const int h   = bh & 31;
    const int kh  = h >> 3;
    const int tid = threadIdx.x;
    const int wm  = tid >> 5;
    const int lane = tid & 31;
    const int gq  = lane >> 2;
    const int qt  = lane & 3;
    const int q0  = qb * 64;

    const uint16_t* Qhp = (const uint16_t*)Qh + ((size_t)bh * T_ + q0) * D_;
    const uint16_t* Qlp = (const uint16_t*)Ql + ((size_t)bh * T_ + q0) * D_;
    const size_t kvoff = ((size_t)(b * HK_ + kh) * T_) * D_;
    const uint16_t* Khp = (const uint16_t*)Kh + kvoff;
    const uint16_t* Klp = (const uint16_t*)Kl + kvoff;
    const uint16_t* Vhp = (const uint16_t*)Vh + kvoff;
    const uint16_t* Vlp = (const uint16_t*)Vl + kvoff;

    const uint32_t sbase = smem_u32(buf);

    {
        int row = tid >> 1;
        int kc  = tid & 1;
#pragma unroll
        for (int g = 0; g < 4; g++) {
            int ch  = kc * 4 + g;
            size_t src = (size_t)row * D_ + ch * 8;
            uint32_t dsthw = row * FP + ch * 8;
            cp_async16(sbase + (FK_HI + dsthw) * 2, Qhp + src);
            cp_async16(sbase + (FK_LO + dsthw) * 2, Qlp + src);
        }
    }
    CP_COMMIT(); CP_WAIT0();
    __syncthreads();

    const int a_row = ((lane >> 3) & 1) * 8 + (lane & 7);
    const int a_k   = (lane >> 4) * 8;
    const int b_row = ((lane >> 4) & 1) * 8 + (lane & 7);
    const int b_k   = ((lane >> 3) & 1) * 8;

    uint32_t qhi[4][4], qlo[4][4];
#pragma unroll
    for (int dk = 0; dk < 4; dk++) {
        int hw = (wm * 16 + a_row) * FP + dk * 16 + a_k;
        ldsm_x4(qhi[dk], sbase + 2 * (FK_HI + hw));
        ldsm_x4(qlo[dk], sbase + 2 * (FK_LO + hw));
    }
    __syncthreads();

    float m0 = -1e30f, m1 = -1e30f, l0 = 0.f, l1 = 0.f;
    float o[8][4];
#pragma unroll
    for (int nf = 0; nf < 8; nf++)
#pragma unroll
        for (int q = 0; q < 4; q++) o[nf][q] = 0.f;

    for (int kb = 0; kb <= qb; kb++) {
        {
            int row = tid >> 1;
            int kc  = tid & 1;
#pragma unroll
            for (int g = 0; g < 4; g++) {
                int ch  = kc * 4 + g;
                size_t src = (size_t)(kb * 64 + row) * D_ + ch * 8;
                uint32_t dsthw = row * FP + ch * 8;
                cp_async16(sbase + (FK_HI + dsthw) * 2, Khp + src);
                cp_async16(sbase + (FK_LO + dsthw) * 2, Klp + src);
            }
        }
        CP_COMMIT();

#pragma unroll
        for (int u2 = 0; u2 < 2; u2++) {
            int u  = tid + u2 * 128;
            int s0 = 2 * (u & 31);
            int d0 = 8 * (u >> 5);
            size_t g0 = (size_t)(kb * 64 + s0) * D_ + d0;
            uint4 h0 = *(const uint4*)(Vhp + g0);
            uint4 h1 = *(const uint4*)(Vhp + g0 + D_);
            uint4 l0v = *(const uint4*)(Vlp + g0);
            uint4 l1v = *(const uint4*)(Vlp + g0 + D_);
            const uint32_t* a0 = (const uint32_t*)&h0;
            const uint32_t* a1 = (const uint32_t*)&h1;
            const uint32_t* c0 = (const uint32_t*)&l0v;
            const uint32_t* c1 = (const uint32_t*)&l1v;
#pragma unroll
            for (int j = 0; j < 4; j++) {
                uint32_t ah = a0[j], bhw = a1[j];
                uint32_t al = c0[j], blw = c1[j];
                int d = d0 + 2 * j;
                *(uint32_t*)&buf[FV_HI + d * FP + s0] = (ah & 0xffffu) | (bhw << 16);
                *(uint32_t*)&buf[FV_HI + (d + 1) * FP + s0] = (ah >> 16) | (bhw & 0xffff0000u);
                *(uint32_t*)&buf[FV_LO + d * FP + s0] = (al & 0xffffu) | (blw << 16);
                *(uint32_t*)&buf[FV_LO + (d + 1) * FP + s0] = (al >> 16) | (blw & 0xffff0000u);
            }
        }
        CP_WAIT0();
        __syncthreads();

        float s[8][4];
#pragma unroll
        for (int nf = 0; nf < 8; nf++)
#pragma unroll
            for (int q = 0; q < 4; q++) s[nf][q] = 0.f;

#pragma unroll
        for (int dk = 0; dk < 4; dk++) {
            uint32_t kfh[4][4], kfl[4][4];
#pragma unroll
            for (int g = 0; g < 4; g++) {
                int hw = (16 * g + b_row) * FP + dk * 16 + b_k;
                ldsm_x4(kfh[g], sbase + 2 * (FK_HI + hw));
                ldsm_x4(kfl[g], sbase + 2 * (FK_LO + hw));
            }
#pragma unroll
            for (int g = 0; g < 4; g++) {
                mma16816(s[2 * g],     qhi[dk], &kfh[g][0]);
                mma16816(s[2 * g],     qhi[dk], &kfl[g][0]);
                mma16816(s[2 * g],     qlo[dk], &kfh[g][0]);
                mma16816(s[2 * g + 1], qhi[dk], &kfh[g][2]);
                mma16816(s[2 * g + 1], qhi[dk], &kfl[g][2]);
                mma16816(s[2 * g + 1], qlo[dk], &kfh[g][2]);
            }
        }

        if (kb == qb) {
            int r0g = 16 * wm + gq;
            int r1g = r0g + 8;
#pragma unroll
            for (int nf = 0; nf < 8; nf++) {
                int c = nf * 8 + 2 * qt;
                if (c     > r0g) s[nf][0] = -1e30f;
                if (c + 1 > r0g) s[nf][1] = -1e30f;
                if (c     > r1g) s[nf][2] = -1e30f;
                if (c + 1 > r1g) s[nf][3] = -1e30f;
            }
        }

        float mx0 = -1e30f, mx1 = -1e30f;
#pragma unroll
        for (int nf = 0; nf < 8; nf++) {
            mx0 = fmaxf(mx0, fmaxf(s[nf][0], s[nf][1]));
            mx1 = fmaxf(mx1, fmaxf(s[nf][2], s[nf][3]));
        }
        mx0 = fmaxf(mx0, __shfl_xor_sync(0xffffffffu, mx0, 1));
        mx0 = fmaxf(mx0, __shfl_xor_sync(0xffffffffu, mx0, 2));
        mx1 = fmaxf(mx1, __shfl_xor_sync(0xffffffffu, mx1, 1));
        mx1 = fmaxf(mx1, __shfl_xor_sync(0xffffffffu, mx1, 2));
        float mn0 = fmaxf(m0, mx0), mn1 = fmaxf(m1, mx1);
        float al0 = __expf(m0 - mn0), al1 = __expf(m1 - mn1);
        float sum0 = 0.f, sum1 = 0.f;
#pragma unroll
        for (int nf = 0; nf < 8; nf++) {
            s[nf][0] = __expf(s[nf][0] - mn0);
            s[nf][1] = __expf(s[nf][1] - mn0);
            s[nf][2] = __expf(s[nf][2] - mn1);
            s[nf][3] = __expf(s[nf][3] - mn1);
            sum0 += s[nf][0] + s[nf][1];
            sum1 += s[nf][2] + s[nf][3];
        }
        sum0 += __shfl_xor_sync(0xffffffffu, sum0, 1);
        sum0 += __shfl_xor_sync(0xffffffffu, sum0, 2);
        sum1 += __shfl_xor_sync(0xffffffffu, sum1, 1);
        sum1 += __shfl_xor_sync(0xffffffffu, sum1, 2);
        l0 = l0 * al0 + sum0;  m0 = mn0;
        l1 = l1 * al1 + sum1;  m1 = mn1;
#pragma unroll
        for (int nf = 0; nf < 8; nf++) {
            o[nf][0] *= al0; o[nf][1] *= al0;
            o[nf][2] *= al1; o[nf][3] *= al1;
        }

        uint32_t phi[4][4], plo[4][4];
#pragma unroll
        for (int kc = 0; kc < 4; kc++) {
            split_pair(s[2 * kc][0],     s[2 * kc][1],     phi[kc][0], plo[kc][0]);
            split_pair(s[2 * kc][2],     s[2 * kc][3],     phi[kc][1], plo[kc][1]);
            split_pair(s[2 * kc + 1][0], s[2 * kc + 1][1], phi[kc][2], plo[kc][2]);
            split_pair(s[2 * kc + 1][2], s[2 * kc + 1][3], phi[kc][3], plo[kc][3]);
        }

#pragma unroll
        for (int kc = 0; kc < 4; kc++) {
            uint32_t vfh[4][4], vfl[4][4];
#pragma unroll
            for (int g = 0; g < 4; g++) {
                int hw = (16 * g + b_row) * FP + kc * 16 + b_k;
                ldsm_x4(vfh[g], sbase + 2 * (FV_HI + hw));
                ldsm_x4(vfl[g], sbase + 2 * (FV_LO + hw));
            }
#pragma unroll
            for (int g = 0; g < 4; g++) {
                mma16816(o[2 * g],     phi[kc], &vfh[g][0]);
                mma16816(o[2 * g],     phi[kc], &vfl[g][0]);
                mma16816(o[2 * g],     plo[kc], &vfh[g][0]);
                mma16816(o[2 * g + 1], phi[kc], &vfh[g][2]);
                mma16816(o[2 * g + 1], phi[kc], &vfl[g][2]);
                mma16816(o[2 * g + 1], plo[kc], &vfh[g][2]);
            }
        }
        __syncthreads();
    }

    float inv0 = 1.0f / l0, inv1 = 1.0f / l1;
    int row0 = q0 + wm * 16 + gq;
    size_t base0 = ((size_t)b * T_ + row0) * (H_ * D_) + h * D_;
    size_t base1 = base0 + (size_t)8 * (H_ * D_);
    uint16_t* OhP = (uint16_t*)Oh;
    uint16_t* OlP = (uint16_t*)Ol;
#pragma unroll
    for (int nf = 0; nf < 8; nf++) {
        int c = nf * 8 + 2 * qt;
        uint32_t hw, lw;
        split_pair(o[nf][0] * inv0, o[nf][1] * inv0, hw, lw);
        *(uint32_t*)(OhP + base0 + c) = hw;
        *(uint32_t*)(OlP + base0 + c) = lw;
        split_pair(o[nf][2] * inv1, o[nf][3] * inv1, hw, lw);
        *(uint32_t*)(OhP + base1 + c) = hw;
        *(uint32_t*)(OlP + base1 + c) = lw;
    }
}

// ===========================================================================
extern "C" void kernel_launch(void* const* d_in, const int* in_sizes, int n_in,
                              void* d_out, int out_size)
{
    const float* x    = (const float*)d_in[0];
    const float* cosT = (const float*)d_in[1];
    const float* sinT = (const float*)d_in[2];
    const float* wq   = (const float*)d_in[3];
    const float* wk   = (const float*)d_in[4];
    const float* wv   = (const float*)d_in[5];
    const float* wo   = (const float*)d_in[6];

    float* out   = (float*)d_out;
    float* out_k = out   + (size_t)B_ * T_ * C_;
    float* out_v = out_k + (size_t)B_ * HK_ * T_ * D_;

    __nv_bfloat16 *xh, *xl, *oh, *ol, *wqh, *wql, *wkh, *wkl, *wvh, *wvl, *woh, *wol;
    __nv_bfloat16 *qh, *ql, *kh, *kl, *vh, *vl;
    cudaGetSymbolAddress((void**)&xh, g_xh);   cudaGetSymbolAddress((void**)&xl, g_xl);
    cudaGetSymbolAddress((void**)&oh, g_oh);   cudaGetSymbolAddress((void**)&ol, g_ol);
    cudaGetSymbolAddress((void**)&wqh, g_wqh); cudaGetSymbolAddress((void**)&wql, g_wql);
    cudaGetSymbolAddress((void**)&wkh, g_wkh); cudaGetSymbolAddress((void**)&wkl, g_wkl);
    cudaGetSymbolAddress((void**)&wvh, g_wvh); cudaGetSymbolAddress((void**)&wvl, g_wvl);
    cudaGetSymbolAddress((void**)&woh, g_woh); cudaGetSymbolAddress((void**)&wol, g_wol);
    cudaGetSymbolAddress((void**)&qh, g_qh);   cudaGetSymbolAddress((void**)&ql, g_ql);
    cudaGetSymbolAddress((void**)&kh, g_kh);   cudaGetSymbolAddress((void**)&kl, g_kl);
    cudaGetSymbolAddress((void**)&vh, g_vh);   cudaGetSymbolAddress((void**)&vl, g_vl);

    cudaFuncSetAttribute(gemm_proj,
                         cudaFuncAttributeMaxDynamicSharedMemorySize, GEMM_SMEM);
    cudaFuncSetAttribute(gemm_out,
                         cudaFuncAttributeMaxDynamicSharedMemorySize, GEMM_SMEM);

    // ---- pre-split inputs into bf16 hi/lo ----
    {
        int nx = (MROWS * C_) / 8;
        int nw = ((H_ * D_) * C_) / 8;
        int ns = ((HK_ * D_) * C_) / 8;
        split_f32<<<(nx + 255) / 256, 256>>>(x,  xh,  xl,  nx);
        split_f32<<<(nw + 255) / 256, 256>>>(wq, wqh, wql, nw);
        split_f32<<<(ns + 255) / 256, 256>>>(wk, wkh, wkl, ns);
        split_f32<<<(ns + 255) / 256, 256>>>(wv, wvh, wvl, ns);
        split_f32<<<(nw + 255) / 256, 256>>>(wo, woh, wol, nw);
    }

    // ---- fused q/k/v projections + RoPE + scatter + split ----
    gemm_proj<<<dim3(20, MROWS / 128), 256, GEMM_SMEM>>>(
        xh, xl, wqh, wql, wkh, wkl, wvh, wvl,
        cosT, sinT, out_k, out_v, qh, ql, kh, kl, vh, vl);

    // ---- flash attention ----
    flash_mma<<<dim3(T_ / 64, B_ * H_), 128>>>(qh, ql, kh, kl, vh, vl, oh, ol);

    // ---- output projection ----
    gemm_out<<<dim3(C_ / 128, MROWS / 128), 256, GEMM_SMEM>>>(oh, ol, woh, wol, out);
}

// round 14
// speedup vs baseline: 1.1165x; 1.0214x over previous
#include <cuda_runtime.h>
#include <cuda_bf16.h>
#include <math.h>
#include <stdint.h>

// Problem constants
#define B_   2
#define T_   2048
#define C_   2048
#define H_   32
#define HK_  4
#define D_   64
#define MROWS (B_ * T_)          // 4096

// ---------------- scratch (static device globals; no allocation) ----------
__device__ __nv_bfloat16 g_xh[(long long)MROWS * C_],  g_xl[(long long)MROWS * C_];
__device__ __nv_bfloat16 g_oh[(long long)MROWS * C_],  g_ol[(long long)MROWS * C_];
__device__ __nv_bfloat16 g_wqh[(long long)(H_*D_) * C_],  g_wql[(long long)(H_*D_) * C_];
__device__ __nv_bfloat16 g_wkh[(long long)(HK_*D_) * C_], g_wkl[(long long)(HK_*D_) * C_];
__device__ __nv_bfloat16 g_wvh[(long long)(HK_*D_) * C_], g_wvl[(long long)(HK_*D_) * C_];
__device__ __nv_bfloat16 g_woh[(long long)C_ * (H_*D_)],  g_wol[(long long)C_ * (H_*D_)];
__device__ __nv_bfloat16 g_qh[(long long)B_*H_*T_*D_],  g_ql[(long long)B_*H_*T_*D_];
__device__ __nv_bfloat16 g_kh[(long long)B_*HK_*T_*D_], g_kl[(long long)B_*HK_*T_*D_];
__device__ __nv_bfloat16 g_vh[(long long)B_*HK_*T_*D_], g_vl[(long long)B_*HK_*T_*D_];

// ===========================================================================
// helpers
// ===========================================================================
__device__ __forceinline__ uint32_t smem_u32(const void* p) {
    uint32_t a;
    asm("{ .reg .u64 t; cvta.to.shared.u64 t, %1; cvt.u32.u64 %0, t; }"
        : "=r"(a) : "l"(p));
    return a;
}
__device__ __forceinline__ void ldsm_x4(uint32_t* r, uint32_t addr) {
    asm volatile("ldmatrix.sync.aligned.m8n8.x4.shared.b16 {%0,%1,%2,%3}, [%4];"
        : "=r"(r[0]), "=r"(r[1]), "=r"(r[2]), "=r"(r[3]) : "r"(addr));
}
__device__ __forceinline__ void mma16816(float* c, const uint32_t* a, const uint32_t* b) {
    asm volatile(
        "mma.sync.aligned.m16n8k16.row.col.f32.bf16.bf16.f32 "
        "{%0,%1,%2,%3}, {%4,%5,%6,%7}, {%8,%9}, {%0,%1,%2,%3};"
        : "+f"(c[0]), "+f"(c[1]), "+f"(c[2]), "+f"(c[3])
        : "r"(a[0]), "r"(a[1]), "r"(a[2]), "r"(a[3]), "r"(b[0]), "r"(b[1]));
}
__device__ __forceinline__ void split_pair(float a, float b, uint32_t& hi, uint32_t& lo) {
    __nv_bfloat162 h = __floats2bfloat162_rn(a, b);
    float ra = a - __bfloat162float(h.x);
    float rb = b - __bfloat162float(h.y);
    __nv_bfloat162 l = __floats2bfloat162_rn(ra, rb);
    hi = *(uint32_t*)&h;
    lo = *(uint32_t*)&l;
}
__device__ __forceinline__ void cp_async16(uint32_t dst, const void* src) {
    asm volatile("cp.async.cg.shared.global [%0], [%1], 16;" :: "r"(dst), "l"(src));
}
#define CP_COMMIT() asm volatile("cp.async.commit_group;" ::: "memory")
#define CP_WAIT1()  asm volatile("cp.async.wait_group 1;" ::: "memory")
#define CP_WAIT0()  asm volatile("cp.async.wait_group 0;" ::: "memory")

// ===========================================================================
// Fused fp32 -> bf16 hi/lo split for ALL five inputs (one launch)
// Regions (in float4x2 groups of 8 floats):
//   x : 1,048,576 | wq : 524,288 | wk : 65,536 | wv : 65,536 | wo : 524,288
// ===========================================================================
#define NX8  1048576
#define NWQ8 524288
#define NWS8 65536
#define SPLIT_TOTAL (NX8 + NWQ8 + 2 * NWS8 + NWQ8)   // 2,228,224

__global__ void split_all(const float* __restrict__ x,  const float* __restrict__ wq,
                          const float* __restrict__ wk, const float* __restrict__ wv,
                          const float* __restrict__ wo,
                          __nv_bfloat16* __restrict__ xh,  __nv_bfloat16* __restrict__ xl,
                          __nv_bfloat16* __restrict__ wqh, __nv_bfloat16* __restrict__ wql,
                          __nv_bfloat16* __restrict__ wkh, __nv_bfloat16* __restrict__ wkl,
                          __nv_bfloat16* __restrict__ wvh, __nv_bfloat16* __restrict__ wvl,
                          __nv_bfloat16* __restrict__ woh, __nv_bfloat16* __restrict__ wol)
{
    long long g = (long long)blockIdx.x * blockDim.x + threadIdx.x;
    if (g >= SPLIT_TOTAL) return;

    const float* src;
    __nv_bfloat16 *hi, *lo;
    long long i = g;
    if (i < NX8)                        { src = x;  hi = xh;  lo = xl; }
    else if ((i -= NX8) < NWQ8)         { src = wq; hi = wqh; lo = wql; }
    else if ((i -= NWQ8) < NWS8)        { src = wk; hi = wkh; lo = wkl; }
    else if ((i -= NWS8) < NWS8)        { src = wv; hi = wvh; lo = wvl; }
    else                                { i -= NWS8; src = wo; hi = woh; lo = wol; }

    const float4* p = (const float4*)src + 2 * (size_t)i;
    float4 f0 = p[0], f1 = p[1];
    uint4 h, l;
    split_pair(f0.x, f0.y, h.x, l.x);
    split_pair(f0.z, f0.w, h.y, l.y);
    split_pair(f1.x, f1.y, h.z, l.z);
    split_pair(f1.z, f1.w, h.w, l.w);
    ((uint4*)hi)[i] = h;
    ((uint4*)lo)[i] = l;
}

// ===========================================================================
// GEMM mainloop (R13): 128x128 block, bf16x3, K=2048, 2-stage cp.async,
// B fragments streamed (fits 128 regs => 2 CTAs/SM).
// ===========================================================================
#define GP 40
#define ST_AHI 0
#define ST_ALO (128 * GP)
#define ST_WHI (2 * 128 * GP)
#define ST_WLO (3 * 128 * GP)
#define STAGE_HW (4 * 128 * GP)          // 20480 hw = 40960 B
#define GEMM_SMEM (2 * STAGE_HW * 2)     // 81920 B

__device__ __forceinline__ void gemm_mainloop(
    const uint16_t* __restrict__ Ahi, const uint16_t* __restrict__ Alo,
    const uint16_t* __restrict__ Whi, const uint16_t* __restrict__ Wlo,
    float acc[2][8][4], int bm, uint16_t* smem)
{
    const int K = C_;
    const uint32_t sbase = smem_u32(smem);
    const int tid  = threadIdx.x;
    const int wid  = tid >> 5;
    const int lane = tid & 31;
    const int wm   = wid & 3;
    const int wn   = wid >> 2;

#pragma unroll
    for (int i = 0; i < 2; i++)
#pragma unroll
        for (int j = 0; j < 8; j++)
#pragma unroll
            for (int q = 0; q < 4; q++) acc[i][j][q] = 0.f;

    const int a_row_in = ((lane >> 3) & 1) * 8 + (lane & 7);
    const int a_koff   = (lane >> 4) * 8;
    const int b_row_in = ((lane >> 4) & 1) * 8 + (lane & 7);
    const int b_koff   = ((lane >> 3) & 1) * 8;

#define GEMM_ISSUE(c) do {                                                    \
        int k0_ = (c) * 32;                                                   \
        uint32_t sb_ = sbase + (((c) & 1) * STAGE_HW) * 2;                     \
        _Pragma("unroll")                                                      \
        for (int r_ = 0; r_ < 2; r_++) {                                      \
            int e_  = tid + r_ * 256;                                          \
            int row = e_ >> 2;                                                 \
            int ch  = e_ & 3;                                                  \
            size_t gA = (size_t)(bm + row) * K + k0_ + ch * 8;                 \
            size_t gW = (size_t)row * K + k0_ + ch * 8;                        \
            uint32_t hwo = (row * GP + ch * 8) * 2;                            \
            cp_async16(sb_ + ST_AHI * 2 + hwo, Ahi + gA);                      \
            cp_async16(sb_ + ST_ALO * 2 + hwo, Alo + gA);                      \
            cp_async16(sb_ + ST_WHI * 2 + hwo, Whi + gW);                      \
            cp_async16(sb_ + ST_WLO * 2 + hwo, Wlo + gW);                      \
        }                                                                      \
    } while (0)

    GEMM_ISSUE(0); CP_COMMIT();

    const int nch = K / 32;
    for (int c = 0; c < nch; c++) {
        if (c + 1 < nch) { GEMM_ISSUE(c + 1); CP_COMMIT(); CP_WAIT1(); }
        else             { CP_WAIT0(); }
        __syncthreads();

        const uint32_t sb = sbase + ((c & 1) * STAGE_HW) * 2;
#pragma unroll
        for (int kk = 0; kk < 32; kk += 16) {
            uint32_t aHi[2][4], aLo[2][4];
#pragma unroll
            for (int mf = 0; mf < 2; mf++) {
                int hw = (wm * 32 + mf * 16 + a_row_in) * GP + kk + a_koff;
                ldsm_x4(aHi[mf], sb + (ST_AHI + hw) * 2);
                ldsm_x4(aLo[mf], sb + (ST_ALO + hw) * 2);
            }
#pragma unroll
            for (int p = 0; p < 4; p++) {
                int hw = (wn * 64 + p * 16 + b_row_in) * GP + kk + b_koff;
                uint32_t rh[4], rl[4];
                ldsm_x4(rh, sb + (ST_WHI + hw) * 2);
                ldsm_x4(rl, sb + (ST_WLO + hw) * 2);
#pragma unroll
                for (int mf = 0; mf < 2; mf++) {
                    mma16816(acc[mf][2 * p],     aHi[mf], &rh[0]);
                    mma16816(acc[mf][2 * p],     aHi[mf], &rl[0]);
                    mma16816(acc[mf][2 * p],     aLo[mf], &rh[0]);
                    mma16816(acc[mf][2 * p + 1], aHi[mf], &rh[2]);
                    mma16816(acc[mf][2 * p + 1], aHi[mf], &rl[2]);
                    mma16816(acc[mf][2 * p + 1], aLo[mf], &rh[2]);
                }
            }
        }
        __syncthreads();
    }
#undef GEMM_ISSUE
}

// ===========================================================================
// Fused q/k/v projection + RoPE + layout scatter + bf16 split (epilogue).
// q scaled by 0.125*log2(e) so flash can use exp2 (base-2 softmax).
// ===========================================================================
#define QSCALE 0.18033688011112042f     // 0.125 * log2(e)

__global__ __launch_bounds__(256, 2)
void gemm_proj(const __nv_bfloat16* __restrict__ xh, const __nv_bfloat16* __restrict__ xl,
               const __nv_bfloat16* __restrict__ wqh, const __nv_bfloat16* __restrict__ wql,
               const __nv_bfloat16* __restrict__ wkh, const __nv_bfloat16* __restrict__ wkl,
               const __nv_bfloat16* __restrict__ wvh, const __nv_bfloat16* __restrict__ wvl,
               const float* __restrict__ cosT, const float* __restrict__ sinT,
               float* __restrict__ out_k, float* __restrict__ out_v,
               __nv_bfloat16* __restrict__ qh, __nv_bfloat16* __restrict__ ql,
               __nv_bfloat16* __restrict__ kh, __nv_bfloat16* __restrict__ kl,
               __nv_bfloat16* __restrict__ vh, __nv_bfloat16* __restrict__ vl)
{
    extern __shared__ __align__(16) uint16_t smem[];
    const int bx = blockIdx.x;
    const int bm = blockIdx.y * 128;

    const uint16_t *Whi, *Wlo;
    int mode, hbase;                 // mode: 0=q, 1=k, 2=v
    if (bx < 16) {
        Whi = (const uint16_t*)wqh + (size_t)bx * 128 * C_;
        Wlo = (const uint16_t*)wql + (size_t)bx * 128 * C_;
        mode = 0; hbase = bx * 2;
    } else if (bx < 18) {
        Whi = (const uint16_t*)wkh + (size_t)(bx - 16) * 128 * C_;
        Wlo = (const uint16_t*)wkl + (size_t)(bx - 16) * 128 * C_;
        mode = 1; hbase = (bx - 16) * 2;
    } else {
        Whi = (const uint16_t*)wvh + (size_t)(bx - 18) * 128 * C_;
        Wlo = (const uint16_t*)wvl + (size_t)(bx - 18) * 128 * C_;
        mode = 2; hbase = (bx - 18) * 2;
    }

    float acc[2][8][4];
    gemm_mainloop((const uint16_t*)xh, (const uint16_t*)xl, Whi, Wlo, acc, bm, smem);

    const int tid  = threadIdx.x;
    const int wid  = tid >> 5;
    const int lane = tid & 31;
    const int wm   = wid & 3;
    const int wn   = wid >> 2;
    const int gq   = lane >> 2;
    const int qt   = lane & 3;
    const int h    = hbase + wn;

#pragma unroll
    for (int mf = 0; mf < 2; mf++) {
        int row0 = bm + wm * 32 + mf * 16 + gq;
        int row1 = row0 + 8;
        int t0 = row0 & (T_ - 1), b0 = row0 >> 11;
        int t1 = row1 & (T_ - 1), b1 = row1 >> 11;
#pragma unroll
        for (int nf = 0; nf < 8; nf++) {
            int d = nf * 8 + qt * 2;                 // even, 0..62
            float v00 = acc[mf][nf][0], v01 = acc[mf][nf][1];
            float v10 = acc[mf][nf][2], v11 = acc[mf][nf][3];
            float o00, o01, o10, o11;
            if (mode == 2) {
                o00 = v00; o01 = v01; o10 = v10; o11 = v11;
            } else {
                float2 c0 = *(const float2*)(cosT + t0 * D_ + d);
                float2 s0 = *(const float2*)(sinT + t0 * D_ + d);
                float2 c1 = *(const float2*)(cosT + t1 * D_ + d);
                float2 s1 = *(const float2*)(sinT + t1 * D_ + d);
                o00 = v00 * c0.x - v01 * s0.x;
                o01 = v01 * c0.y + v00 * s0.y;
                o10 = v10 * c1.x - v11 * s1.x;
                o11 = v11 * c1.y + v10 * s1.y;
                if (mode == 0) { o00 *= QSCALE; o01 *= QSCALE;
                                 o10 *= QSCALE; o11 *= QSCALE; }
            }
            uint32_t hw, lw;
            if (mode == 0) {
                size_t i0 = (((size_t)b0 * H_ + h) * T_ + t0) * D_ + d;
                size_t i1 = (((size_t)b1 * H_ + h) * T_ + t1) * D_ + d;
                split_pair(o00, o01, hw, lw);
                *(uint32_t*)((uint16_t*)qh + i0) = hw;
                *(uint32_t*)((uint16_t*)ql + i0) = lw;
                split_pair(o10, o11, hw, lw);
                *(uint32_t*)((uint16_t*)qh + i1) = hw;
                *(uint32_t*)((uint16_t*)ql + i1) = lw;
            } else {
                size_t i0 = (((size_t)b0 * HK_ + h) * T_ + t0) * D_ + d;
                size_t i1 = (((size_t)b1 * HK_ + h) * T_ + t1) * D_ + d;
                float* outF = (mode == 1) ? out_k : out_v;
                uint16_t* dH = (mode == 1) ? (uint16_t*)kh : (uint16_t*)vh;
                uint16_t* dL = (mode == 1) ? (uint16_t*)kl : (uint16_t*)vl;
                *(float2*)(outF + i0) = make_float2(o00, o01);
                *(float2*)(outF + i1) = make_float2(o10, o11);
                split_pair(o00, o01, hw, lw);
                *(uint32_t*)(dH + i0) = hw;
                *(uint32_t*)(dL + i0) = lw;
                split_pair(o10, o11, hw, lw);
                *(uint32_t*)(dH + i1) = hw;
                *(uint32_t*)(dL + i1) = lw;
            }
        }
    }
}

// Output projection: standard fp32 store
__global__ __launch_bounds__(256, 2)
void gemm_out(const __nv_bfloat16* __restrict__ oh, const __nv_bfloat16* __restrict__ ol,
              const __nv_bfloat16* __restrict__ woh, const __nv_bfloat16* __restrict__ wol,
              float* __restrict__ out)
{
    extern __shared__ __align__(16) uint16_t smem[];
    const int bm = blockIdx.y * 128;
    const int bn = blockIdx.x * 128;
    float acc[2][8][4];
    gemm_mainloop((const uint16_t*)oh, (const uint16_t*)ol,
                  (const uint16_t*)woh + (size_t)bn * C_,
                  (const uint16_t*)wol + (size_t)bn * C_,
                  acc, bm, smem);

    const int tid  = threadIdx.x;
    const int wid  = tid >> 5;
    const int lane = tid & 31;
    const int wm   = wid & 3;
    const int wn   = wid >> 2;
    const int gq   = lane >> 2;
    const int qt   = lane & 3;
#pragma unroll
    for (int mf = 0; mf < 2; mf++) {
#pragma unroll
        for (int nf = 0; nf < 8; nf++) {
            int row0 = bm + wm * 32 + mf * 16 + gq;
            int col  = bn + wn * 64 + nf * 8 + qt * 2;
            *(float2*)(out + (size_t)row0 * C_ + col) =
                make_float2(acc[mf][nf][0], acc[mf][nf][1]);
            *(float2*)(out + (size_t)(row0 + 8) * C_ + col) =
                make_float2(acc[mf][nf][2], acc[mf][nf][3]);
        }
    }
}

// ===========================================================================
// Tensor-core causal flash attention: Br=64, 128 threads, base-2 softmax,
// LPT block order (heaviest q-blocks launched first).
// ===========================================================================
#define FP 72
#define FK_HI 0
#define FK_LO 4608
#define FV_HI 9216
#define FV_LO 13824

__global__ __launch_bounds__(128)
void flash_mma(const __nv_bfloat16* __restrict__ Qh, const __nv_bfloat16* __restrict__ Ql,
               const __nv_bfloat16* __restrict__ Kh, const __nv_bfloat16* __restrict__ Kl,
               const __nv_bfloat16* __restrict__ Vh, const __nv_bfloat16* __restrict__ Vl,
               __nv_bfloat16* __restrict__ Oh, __nv_bfloat16* __restrict__ Ol)
{
    __shared__ __align__(16) uint16_t buf[18432];

    const int qb  = (T_ / 64 - 1) - blockIdx.x;      // LPT: big blocks first
    const int bh  = blockIdx.y;
    const int b   = bh >> 5;
    const int h   = bh & 31;
    const int kh  = h >> 3;
    const int tid = threadIdx.x;
    const int wm  = tid >> 5;
    const int lane = tid & 31;
    const int gq  = lane >> 2;
    const int qt  = lane & 3;
    const int q0  = qb * 64;

    const uint16_t* Qhp = (const uint16_t*)Qh + ((size_t)bh * T_ + q0) * D_;
    const uint16_t* Qlp = (const uint16_t*)Ql + ((size_t)bh * T_ + q0) * D_;
    const size_t kvoff = ((size_t)(b * HK_ + kh) * T_) * D_;
    const uint16_t* Khp = (const uint16_t*)Kh + kvoff;
    const uint16_t* Klp = (const uint16_t*)Kl + kvoff;
    const uint16_t* Vhp = (const uint16_t*)Vh + kvoff;
    const uint16_t* Vlp = (const uint16_t*)Vl + kvoff;

    const uint32_t sbase = smem_u32(buf);

    {
        int row = tid >> 1;
        int kc  = tid & 1;
#pragma unroll
        for (int g = 0; g < 4; g++) {
            int ch  = kc * 4 + g;
            size_t src = (size_t)row * D_ + ch * 8;
            uint32_t dsthw = row * FP + ch * 8;
            cp_async16(sbase + (FK_HI + dsthw) * 2, Qhp + src);
            cp_async16(sbase + (FK_LO + dsthw) * 2, Qlp + src);
        }
    }
    CP_COMMIT(); CP_WAIT0();
    __syncthreads();

    const int a_row = ((lane >> 3) & 1) * 8 + (lane & 7);
    const int a_k   = (lane >> 4) * 8;
    const int b_row = ((lane >> 4) & 1) * 8 + (lane & 7);
    const int b_k   = ((lane >> 3) & 1) * 8;

    uint32_t qhi[4][4], qlo[4][4];
#pragma unroll
    for (int dk = 0; dk < 4; dk++) {
        int hw = (wm * 16 + a_row) * FP + dk * 16 + a_k;
        ldsm_x4(qhi[dk], sbase + 2 * (FK_HI + hw));
        ldsm_x4(qlo[dk], sbase + 2 * (FK_LO + hw));
    }
    __syncthreads();

    float m0 = -1e30f, m1 = -1e30f, l0 = 0.f, l1 = 0.f;
    float o[8][4];
#pragma unroll
    for (int nf = 0; nf < 8; nf++)
#pragma unroll
        for (int q = 0; q < 4; q++) o[nf][q] = 0.f;

    for (int kb = 0; kb <= qb; kb++) {
        {
            int row = tid >> 1;
            int kc  = tid & 1;
#pragma unroll
            for (int g = 0; g < 4; g++) {
                int ch  = kc * 4 + g;
                size_t src = (size_t)(kb * 64 + row) * D_ + ch * 8;
                uint32_t dsthw = row * FP + ch * 8;
                cp_async16(sbase + (FK_HI + dsthw) * 2, Khp + src);
                cp_async16(sbase + (FK_LO + dsthw) * 2, Klp + src);
            }
        }
        CP_COMMIT();

#pragma unroll
        for (int u2 = 0; u2 < 2; u2++) {
            int u  = tid + u2 * 128;
            int s0 = 2 * (u & 31);
            int d0 = 8 * (u >> 5);
            size_t g0 = (size_t)(kb * 64 + s0) * D_ + d0;
            uint4 h0 = *(const uint4*)(Vhp + g0);
            uint4 h1 = *(const uint4*)(Vhp + g0 + D_);
            uint4 l0v = *(const uint4*)(Vlp + g0);
            uint4 l1v = *(const uint4*)(Vlp + g0 + D_);
            const uint32_t* a0 = (const uint32_t*)&h0;
            const uint32_t* a1 = (const uint32_t*)&h1;
            const uint32_t* c0 = (const uint32_t*)&l0v;
            const uint32_t* c1 = (const uint32_t*)&l1v;
#pragma unroll
            for (int j = 0; j < 4; j++) {
                uint32_t ah = a0[j], bhw = a1[j];
                uint32_t al = c0[j], blw = c1[j];
                int d = d0 + 2 * j;
                *(uint32_t*)&buf[FV_HI + d * FP + s0] = (ah & 0xffffu) | (bhw << 16);
                *(uint32_t*)&buf[FV_HI + (d + 1) * FP + s0] = (ah >> 16) | (bhw & 0xffff0000u);
                *(uint32_t*)&buf[FV_LO + d * FP + s0] = (al & 0xffffu) | (blw << 16);
                *(uint32_t*)&buf[FV_LO + (d + 1) * FP + s0] = (al >> 16) | (blw & 0xffff0000u);
            }
        }
        CP_WAIT0();
        __syncthreads();

        float s[8][4];
#pragma unroll
        for (int nf = 0; nf < 8; nf++)
#pragma unroll
            for (int q = 0; q < 4; q++) s[nf][q] = 0.f;

#pragma unroll
        for (int dk = 0; dk < 4; dk++) {
            uint32_t kfh[4][4], kfl[4][4];
#pragma unroll
            for (int g = 0; g < 4; g++) {
                int hw = (16 * g + b_row) * FP + dk * 16 + b_k;
                ldsm_x4(kfh[g], sbase + 2 * (FK_HI + hw));
                ldsm_x4(kfl[g], sbase + 2 * (FK_LO + hw));
            }
#pragma unroll
            for (int g = 0; g < 4; g++) {
                mma16816(s[2 * g],     qhi[dk], &kfh[g][0]);
                mma16816(s[2 * g],     qhi[dk], &kfl[g][0]);
                mma16816(s[2 * g],     qlo[dk], &kfh[g][0]);
                mma16816(s[2 * g + 1], qhi[dk], &kfh[g][2]);
                mma16816(s[2 * g + 1], qhi[dk], &kfl[g][2]);
                mma16816(s[2 * g + 1], qlo[dk], &kfh[g][2]);
            }
        }

        if (kb == qb) {
            int r0g = 16 * wm + gq;
            int r1g = r0g + 8;
#pragma unroll
            for (int nf = 0; nf < 8; nf++) {
                int c = nf * 8 + 2 * qt;
                if (c     > r0g) s[nf][0] = -1e30f;
                if (c + 1 > r0g) s[nf][1] = -1e30f;
                if (c     > r1g) s[nf][2] = -1e30f;
                if (c + 1 > r1g) s[nf][3] = -1e30f;
            }
        }

        // ---- online softmax (base 2; q pre-scaled by log2e) ----
        float mx0 = -1e30f, mx1 = -1e30f;
#pragma unroll
        for (int nf = 0; nf < 8; nf++) {
            mx0 = fmaxf(mx0, fmaxf(s[nf][0], s[nf][1]));
            mx1 = fmaxf(mx1, fmaxf(s[nf][2], s[nf][3]));
        }
        mx0 = fmaxf(mx0, __shfl_xor_sync(0xffffffffu, mx0, 1));
        mx0 = fmaxf(mx0, __shfl_xor_sync(0xffffffffu, mx0, 2));
        mx1 = fmaxf(mx1, __shfl_xor_sync(0xffffffffu, mx1, 1));
        mx1 = fmaxf(mx1, __shfl_xor_sync(0xffffffffu, mx1, 2));
        float mn0 = fmaxf(m0, mx0), mn1 = fmaxf(m1, mx1);
        float al0 = exp2f(m0 - mn0), al1 = exp2f(m1 - mn1);
        float sum0 = 0.f, sum1 = 0.f;
#pragma unroll
        for (int nf = 0; nf < 8; nf++) {
            s[nf][0] = exp2f(s[nf][0] - mn0);
            s[nf][1] = exp2f(s[nf][1] - mn0);
            s[nf][2] = exp2f(s[nf][2] - mn1);
            s[nf][3] = exp2f(s[nf][3] - mn1);
            sum0 += s[nf][0] + s[nf][1];
            sum1 += s[nf][2] + s[nf][3];
        }
        sum0 += __shfl_xor_sync(0xffffffffu, sum0, 1);
        sum0 += __shfl_xor_sync(0xffffffffu, sum0, 2);
        sum1 += __shfl_xor_sync(0xffffffffu, sum1, 1);
        sum1 += __shfl_xor_sync(0xffffffffu, sum1, 2);
        l0 = l0 * al0 + sum0;  m0 = mn0;
        l1 = l1 * al1 + sum1;  m1 = mn1;
#pragma unroll
        for (int nf = 0; nf < 8; nf++) {
            o[nf][0] *= al0; o[nf][1] *= al0;
            o[nf][2] *= al1; o[nf][3] *= al1;
        }

        uint32_t phi[4][4], plo[4][4];
#pragma unroll
        for (int kc = 0; kc < 4; kc++) {
            split_pair(s[2 * kc][0],     s[2 * kc][1],     phi[kc][0], plo[kc][0]);
            split_pair(s[2 * kc][2],     s[2 * kc][3],     phi[kc][1], plo[kc][1]);
            split_pair(s[2 * kc + 1][0], s[2 * kc + 1][1], phi[kc][2], plo[kc][2]);
            split_pair(s[2 * kc + 1][2], s[2 * kc + 1][3], phi[kc][3], plo[kc][3]);
        }

#pragma unroll
        for (int kc = 0; kc < 4; kc++) {
            uint32_t vfh[4][4], vfl[4][4];
#pragma unroll
            for (int g = 0; g < 4; g++) {
                int hw = (16 * g + b_row) * FP + kc * 16 + b_k;
                ldsm_x4(vfh[g], sbase + 2 * (FV_HI + hw));
                ldsm_x4(vfl[g], sbase + 2 * (FV_LO + hw));
            }
#pragma unroll
            for (int g = 0; g < 4; g++) {
                mma16816(o[2 * g],     phi[kc], &vfh[g][0]);
                mma16816(o[2 * g],     phi[kc], &vfl[g][0]);
                mma16816(o[2 * g],     plo[kc], &vfh[g][0]);
                mma16816(o[2 * g + 1], phi[kc], &vfh[g][2]);
                mma16816(o[2 * g + 1], phi[kc], &vfl[g][2]);
                mma16816(o[2 * g + 1], plo[kc], &vfh[g][2]);
            }
        }
        __syncthreads();
    }

    float inv0 = 1.0f / l0, inv1 = 1.0f / l1;
    int row0 = q0 + wm * 16 + gq;
    size_t base0 = ((size_t)b * T_ + row0) * (H_ * D_) + h * D_;
    size_t base1 = base0 + (size_t)8 * (H_ * D_);
    uint16_t* OhP = (uint16_t*)Oh;
    uint16_t* OlP = (uint16_t*)Ol;
#pragma unroll
    for (int nf = 0; nf < 8; nf++) {
        int c = nf * 8 + 2 * qt;
        uint32_t hw, lw;
        split_pair(o[nf][0] * inv0, o[nf][1] * inv0, hw, lw);
        *(uint32_t*)(OhP + base0 + c) = hw;
        *(uint32_t*)(OlP + base0 + c) = lw;
        split_pair(o[nf][2] * inv1, o[nf][3] * inv1, hw, lw);
        *(uint32_t*)(OhP + base1 + c) = hw;
        *(uint32_t*)(OlP + base1 + c) = lw;
    }
}

// ===========================================================================
extern "C" void kernel_launch(void* const* d_in, const int* in_sizes, int n_in,
                              void* d_out, int out_size)
{
    const float* x    = (const float*)d_in[0];
    const float* cosT = (const float*)d_in[1];
    const float* sinT = (const float*)d_in[2];
    const float* wq   = (const float*)d_in[3];
    const float* wk   = (const float*)d_in[4];
    const float* wv   = (const float*)d_in[5];
    const float* wo   = (const float*)d_in[6];

    float* out   = (float*)d_out;
    float* out_k = out   + (size_t)B_ * T_ * C_;
    float* out_v = out_k + (size_t)B_ * HK_ * T_ * D_;

    __nv_bfloat16 *xh, *xl, *oh, *ol, *wqh, *wql, *wkh, *wkl, *wvh, *wvl, *woh, *wol;
    __nv_bfloat16 *qh, *ql, *kh, *kl, *vh, *vl;
    cudaGetSymbolAddress((void**)&xh, g_xh);   cudaGetSymbolAddress((void**)&xl, g_xl);
    cudaGetSymbolAddress((void**)&oh, g_oh);   cudaGetSymbolAddress((void**)&ol, g_ol);
    cudaGetSymbolAddress((void**)&wqh, g_wqh); cudaGetSymbolAddress((void**)&wql, g_wql);
    cudaGetSymbolAddress((void**)&wkh, g_wkh); cudaGetSymbolAddress((void**)&wkl, g_wkl);
    cudaGetSymbolAddress((void**)&wvh, g_wvh); cudaGetSymbolAddress((void**)&wvl, g_wvl);
    cudaGetSymbolAddress((void**)&woh, g_woh); cudaGetSymbolAddress((void**)&wol, g_wol);
    cudaGetSymbolAddress((void**)&qh, g_qh);   cudaGetSymbolAddress((void**)&ql, g_ql);
    cudaGetSymbolAddress((void**)&kh, g_kh);   cudaGetSymbolAddress((void**)&kl, g_kl);
    cudaGetSymbolAddress((void**)&vh, g_vh);   cudaGetSymbolAddress((void**)&vl, g_vl);

    cudaFuncSetAttribute(gemm_proj,
                         cudaFuncAttributeMaxDynamicSharedMemorySize, GEMM_SMEM);
    cudaFuncSetAttribute(gemm_out,
                         cudaFuncAttributeMaxDynamicSharedMemorySize, GEMM_SMEM);

    // ---- pre-split all inputs into bf16 hi/lo (one launch) ----
    split_all<<<(SPLIT_TOTAL + 255) / 256, 256>>>(
        x, wq, wk, wv, wo,
        xh, xl, wqh, wql, wkh, wkl, wvh, wvl, woh, wol);

    // ---- fused q/k/v projections + RoPE + scatter + split ----
    gemm_proj<<<dim3(20, MROWS / 128), 256, GEMM_SMEM>>>(
        xh, xl, wqh, wql, wkh, wkl, wvh, wvl,
        cosT, sinT, out_k, out_v, qh, ql, kh, kl, vh, vl);

    // ---- flash attention (LPT order, base-2 softmax) ----
    flash_mma<<<dim3(T_ / 64, B_ * H_), 128>>>(qh, ql, kh, kl, vh, vl, oh, ol);

    // ---- output projection ----
    gemm_out<<<dim3(C_ / 128, MROWS / 128), 256, GEMM_SMEM>>>(oh, ol, woh, wol, out);
}